// round 1
// baseline (speedup 1.0000x reference)
#include <cuda_runtime.h>

// Problem constants (fixed by the dataset shapes)
#define N_B    32
#define C_DIM  512
#define T_DIM  1024
#define D_DIM  512          // code_dim == C
#define K_CODES 1024        // 32*32 SOM grid
#define M_ROWS 32768        // N*T

// Output layout (concatenation of reference return tuple, fp32)
#define O_ZQST   0UL
#define O_COMMIT 16777216UL
#define O_SOM    16777217UL
#define O_NB     16777218UL
#define O_DIST   100663298UL
#define O_K      134217730UL

#define NUM_GATHER_BLOCKS 2048   // (T/16) * N = 64*32

// Scratch (no allocations allowed)
static __device__ float g_zsq[M_ROWS];
static __device__ float g_esq[K_CODES];
static __device__ int   g_k[M_ROWS];
static __device__ float g_cpart[NUM_GATHER_BLOCKS];
static __device__ float g_spart[NUM_GATHER_BLOCKS];

// ---------------------------------------------------------------------------
// Kernel 1: z_sq[m] = sum_d x[n,d,t]^2   (m = n*T + t)
// Consecutive threads = consecutive t -> coalesced loads.
// ---------------------------------------------------------------------------
__global__ void zsq_kernel(const float* __restrict__ x) {
    int m = blockIdx.x * 256 + threadIdx.x;
    int n = m >> 10;
    int t = m & 1023;
    const float* xp = x + (size_t)n * C_DIM * T_DIM + t;
    float acc = 0.f;
#pragma unroll 8
    for (int d = 0; d < D_DIM; d++) {
        float v = xp[(size_t)d * T_DIM];
        acc += v * v;
    }
    g_zsq[m] = acc;
}

// ---------------------------------------------------------------------------
// Kernel 2: e_sq[k] = sum_d E[k,d]^2. One block per code, fixed-order reduce.
// ---------------------------------------------------------------------------
__global__ void esq_kernel(const float* __restrict__ E) {
    __shared__ float red[128];
    int code = blockIdx.x;
    const float* e = E + (size_t)code * D_DIM;
    float acc = 0.f;
    for (int d = threadIdx.x; d < D_DIM; d += 128) {
        float v = e[d];
        acc += v * v;
    }
    red[threadIdx.x] = acc;
    __syncthreads();
    for (int s = 64; s > 0; s >>= 1) {
        if (threadIdx.x < s) red[threadIdx.x] += red[threadIdx.x + s];
        __syncthreads();
    }
    if (threadIdx.x == 0) g_esq[code] = red[0];
}

// ---------------------------------------------------------------------------
// Kernel 3: distance GEMM + per-row argmin.
// Block = 128 rows x (all 1024 codes, in 128-code chunks). 256 threads,
// 8x8 register tile, BK=16. dist = zsq - 2*dot + esq, written per chunk.
// Block-local argmin with first-occurrence tie-break (matches jnp.argmin).
// ---------------------------------------------------------------------------
__global__ __launch_bounds__(256, 2) void dist_kernel(
    const float* __restrict__ x, const float* __restrict__ E,
    float* __restrict__ out)
{
    __shared__ float zs[16][128];
    __shared__ float es[16][132];      // pad 4 to spread banks
    __shared__ float rdist[128][16];
    __shared__ int   ridx[128][16];

    int tid = threadIdx.x;
    int m0 = blockIdx.x * 128;
    int n = m0 >> 10;
    int t0 = m0 & 1023;
    const float* xn = x + (size_t)n * C_DIM * T_DIM + t0;
    int tx = tid & 15;       // code sub-tile
    int ty = tid >> 4;       // row sub-tile
    int dl = tid & 15;       // loader: d lane for E
    int cg = tid >> 4;       // loader: code group for E

    float bestD[8];
    int   bestI[8];
    float zsq_r[8];
#pragma unroll
    for (int i = 0; i < 8; i++) {
        bestD[i] = 3.4e38f;
        bestI[i] = 0;
        zsq_r[i] = g_zsq[m0 + ty * 8 + i];
    }

    float* o_dist = out + O_DIST;

    for (int c0 = 0; c0 < K_CODES; c0 += 128) {
        float acc[8][8];
#pragma unroll
        for (int i = 0; i < 8; i++)
#pragma unroll
            for (int j = 0; j < 8; j++) acc[i][j] = 0.f;

        for (int d0 = 0; d0 < D_DIM; d0 += 16) {
            __syncthreads();
            // load z tile: [16 d][128 m], coalesced along m (=t)
#pragma unroll
            for (int i = 0; i < 8; i++) {
                int idx = tid + i * 256;
                zs[idx >> 7][idx & 127] =
                    xn[(size_t)(d0 + (idx >> 7)) * T_DIM + (idx & 127)];
            }
            // load E tile: [16 d][128 codes], coalesced along d (64B rows)
#pragma unroll
            for (int i = 0; i < 8; i++) {
                int c = cg + i * 16;
                es[dl][c] = E[(size_t)(c0 + c) * D_DIM + d0 + dl];
            }
            __syncthreads();
#pragma unroll
            for (int kk = 0; kk < 16; kk++) {
                float a[8], b[8];
#pragma unroll
                for (int i = 0; i < 8; i++) a[i] = zs[kk][ty * 8 + i];
#pragma unroll
                for (int j = 0; j < 8; j++) b[j] = es[kk][tx * 8 + j];
#pragma unroll
                for (int i = 0; i < 8; i++)
#pragma unroll
                    for (int j = 0; j < 8; j++) acc[i][j] += a[i] * b[j];
            }
        }

        // epilogue for this code chunk
        float esq_c[8];
#pragma unroll
        for (int j = 0; j < 8; j++) esq_c[j] = g_esq[c0 + tx * 8 + j];
#pragma unroll
        for (int i = 0; i < 8; i++) {
            int row = m0 + ty * 8 + i;
            float* dst = o_dist + (size_t)row * K_CODES + c0 + tx * 8;
#pragma unroll
            for (int j = 0; j < 8; j++) {
                float dv = zsq_r[i] - 2.f * acc[i][j] + esq_c[j];
                dst[j] = dv;
                // strict < with ascending scan order -> first-min wins
                if (dv < bestD[i]) { bestD[i] = dv; bestI[i] = c0 + tx * 8 + j; }
            }
        }
    }

    __syncthreads();
#pragma unroll
    for (int i = 0; i < 8; i++) {
        rdist[ty * 8 + i][tx] = bestD[i];
        ridx[ty * 8 + i][tx]  = bestI[i];
    }
    __syncthreads();
    if (tid < 128) {
        float bd = rdist[tid][0];
        int   bi = ridx[tid][0];
#pragma unroll
        for (int q = 1; q < 16; q++) {
            float dq = rdist[tid][q];
            int   iq = ridx[tid][q];
            if (dq < bd || (dq == bd && iq < bi)) { bd = dq; bi = iq; }
        }
        int m = m0 + tid;
        g_k[m] = bi;
        out[O_K + m] = (float)bi;
    }
}

// ---------------------------------------------------------------------------
// Kernel 4: gather z_q + 4 SOM neighbors, write z_q_st (=z_q, transposed),
// z_q_neighbors, and accumulate loss partials. Block = (n, 16 t's).
// z_e staged through SMEM so neighbor writes are coalesced along d and
// z_q_st writes are coalesced along t. E-row gathers are coalesced & L2-hot.
// ---------------------------------------------------------------------------
__global__ void gather_kernel(const float* __restrict__ x,
                              const float* __restrict__ E,
                              float* __restrict__ out)
{
    __shared__ float s[512][17];       // [d][t], padded
    __shared__ int   s_code[16][5];
    __shared__ float s_mask[16][5];
    __shared__ float red[256];

    int tid = threadIdx.x;
    int lane = tid & 15;     // t within tile
    int dgrp = tid >> 4;     // d group
    int n = blockIdx.y;
    int t0 = blockIdx.x * 16;
    const float* xp = x + (size_t)n * C_DIM * T_DIM + t0;

    // stage z_e tile (coalesced 64B rows)
    for (int d = dgrp; d < 512; d += 16)
        s[d][lane] = xp[(size_t)d * T_DIM + lane];

    if (tid < 16) {
        int m = n * T_DIM + t0 + tid;
        int kk = g_k[m];
        int k1 = kk >> 5, k2 = kk & 31;
        s_code[tid][0] = kk;              s_mask[tid][0] = 1.f;
        s_code[tid][1] = (k1 + 1) * 32 + k2; s_mask[tid][1] = (k1 < 31) ? 1.f : 0.f; // up
        s_code[tid][2] = (k1 - 1) * 32 + k2; s_mask[tid][2] = (k1 > 0)  ? 1.f : 0.f; // down
        s_code[tid][3] = kk + 1;             s_mask[tid][3] = (k2 < 31) ? 1.f : 0.f; // right
        s_code[tid][4] = kk - 1;             s_mask[tid][4] = (k2 > 0)  ? 1.f : 0.f; // left
    }
    __syncthreads();

    float cacc = 0.f, sacc = 0.f;
    for (int t = 0; t < 16; t++) {
        int m = n * T_DIM + t0 + t;
        float* nbp = out + O_NB + (size_t)m * (5 * 512);
        int code0 = s_code[t][0];
#pragma unroll
        for (int pass = 0; pass < 2; pass++) {
            int d = tid + pass * 256;
            float ze = s[d][t];
            float zq = E[(size_t)code0 * 512 + d];
            nbp[d] = zq;
            float diff = zq - ze;
            cacc += diff * diff;        // commit term
            sacc += diff * diff;        // som slot 0
#pragma unroll
            for (int slot = 1; slot < 5; slot++) {
                float msk = s_mask[t][slot];
                float v = 0.f;
                if (msk != 0.f) v = E[(size_t)s_code[t][slot] * 512 + d];
                nbp[slot * 512 + d] = v;
                float dd = ze - v;
                sacc += dd * dd;
            }
            s[d][t] = zq;               // in-place: this cell is done with ze
        }
    }
    __syncthreads();

    // z_q_st[n, d, t] = z_q  (coalesced along t)
    for (int d = dgrp; d < 512; d += 16)
        out[O_ZQST + (size_t)n * C_DIM * T_DIM + (size_t)d * T_DIM + t0 + lane]
            = s[d][lane];

    // fixed-order block reductions -> partials
    red[tid] = cacc;
    __syncthreads();
    for (int sft = 128; sft > 0; sft >>= 1) {
        if (tid < sft) red[tid] += red[tid + sft];
        __syncthreads();
    }
    float cblock = red[0];
    __syncthreads();
    red[tid] = sacc;
    __syncthreads();
    for (int sft = 128; sft > 0; sft >>= 1) {
        if (tid < sft) red[tid] += red[tid + sft];
        __syncthreads();
    }
    if (tid == 0) {
        int bid = blockIdx.y * gridDim.x + blockIdx.x;
        g_cpart[bid] = cblock;
        g_spart[bid] = red[0];
    }
}

// ---------------------------------------------------------------------------
// Kernel 5: deterministic final loss reduce (double precision, fixed order).
// ---------------------------------------------------------------------------
__global__ void loss_kernel(float* __restrict__ out) {
    __shared__ double rc[256], rs[256];
    int tid = threadIdx.x;
    double c = 0.0, s = 0.0;
    for (int i = tid; i < NUM_GATHER_BLOCKS; i += 256) {
        c += (double)g_cpart[i];
        s += (double)g_spart[i];
    }
    rc[tid] = c; rs[tid] = s;
    __syncthreads();
    for (int sft = 128; sft > 0; sft >>= 1) {
        if (tid < sft) { rc[tid] += rc[tid + sft]; rs[tid] += rs[tid + sft]; }
        __syncthreads();
    }
    if (tid == 0) {
        double MD = (double)M_ROWS * (double)D_DIM;
        out[O_COMMIT] = (float)(2.0 * rc[0] / MD);
        out[O_SOM]    = (float)(rs[0] / (MD * 5.0));
    }
}

// ---------------------------------------------------------------------------
extern "C" void kernel_launch(void* const* d_in, const int* in_sizes, int n_in,
                              void* d_out, int out_size) {
    const float* x = (const float*)d_in[0];        // (32, 512, 1024)
    const float* E = (const float*)d_in[1];        // (32, 32, 512) -> (1024, 512)
    float* out = (float*)d_out;

    zsq_kernel<<<M_ROWS / 256, 256>>>(x);
    esq_kernel<<<K_CODES, 128>>>(E);
    dist_kernel<<<M_ROWS / 128, 256>>>(x, E, out);
    dim3 g(T_DIM / 16, N_B);
    gather_kernel<<<g, 256>>>(x, E, out);
    loss_kernel<<<1, 256>>>(out);
}

// round 5
// speedup vs baseline: 1.8451x; 1.8451x over previous
#include <cuda_runtime.h>
#include <cuda_bf16.h>
#include <cstdint>

// Problem constants
#define N_B    32
#define C_DIM  512
#define T_DIM  1024
#define D_DIM  512
#define K_CODES 1024
#define M_ROWS 32768

// Output layout (concatenation of reference return tuple, fp32)
#define O_ZQST   0UL
#define O_COMMIT 16777216UL
#define O_SOM    16777217UL
#define O_NB     16777218UL
#define O_DIST   100663298UL
#define O_K      134217730UL

#define NUM_GATHER_BLOCKS 2048

// ---------------- scratch (device globals; no allocations) ----------------
static __device__ float g_zsq[M_ROWS];
static __device__ float g_esq[K_CODES];
static __device__ int   g_k[M_ROWS];
static __device__ unsigned long long g_key[M_ROWS];
static __device__ float g_cpart[NUM_GATHER_BLOCKS];
static __device__ float g_spart[NUM_GATHER_BLOCKS];

// bf16 2-way split operands + contiguous fp32 transposed z (for exact fixup)
static __device__ __nv_bfloat16 g_z1[M_ROWS * D_DIM];
static __device__ __nv_bfloat16 g_z2[M_ROWS * D_DIM];
static __device__ __nv_bfloat16 g_e1[K_CODES * D_DIM];
static __device__ __nv_bfloat16 g_e2[K_CODES * D_DIM];
static __device__ float g_zt[M_ROWS * D_DIM];

// ---------------- PTX helpers (baseline sm_80+ PTX, valid on compute_103) ----
__device__ __forceinline__ void cp16(uint32_t dst, const void* src) {
    asm volatile("cp.async.cg.shared.global [%0], [%1], 16;" :: "r"(dst), "l"(src));
}
#define CP_COMMIT() asm volatile("cp.async.commit_group;" ::: "memory")
#define CP_WAIT2()  asm volatile("cp.async.wait_group 2;" ::: "memory")

#define LDSM4(r0, r1, r2, r3, addr)                                        \
    asm volatile("ldmatrix.sync.aligned.m8n8.x4.shared.b16 {%0,%1,%2,%3}, [%4];" \
                 : "=r"(r0), "=r"(r1), "=r"(r2), "=r"(r3) : "r"(addr))

__device__ __forceinline__ void mma16816(float* c, const uint32_t* a, const uint32_t* b) {
    asm volatile(
        "mma.sync.aligned.m16n8k16.row.col.f32.bf16.bf16.f32 "
        "{%0,%1,%2,%3}, {%4,%5,%6,%7}, {%8,%9}, {%0,%1,%2,%3};"
        : "+f"(c[0]), "+f"(c[1]), "+f"(c[2]), "+f"(c[3])
        : "r"(a[0]), "r"(a[1]), "r"(a[2]), "r"(a[3]), "r"(b[0]), "r"(b[1]));
}

// ---------------------------------------------------------------------------
// Prep: transpose x -> z rows (m-major), 2-way bf16 split + fp32 copy
// ---------------------------------------------------------------------------
__global__ void prep_z_kernel(const float* __restrict__ x) {
    __shared__ float s[64][33];
    int tid = threadIdx.x;
    int t0 = blockIdx.x * 32, d0 = blockIdx.y * 64, n = blockIdx.z;
    const float* xp = x + (size_t)n * C_DIM * T_DIM + (size_t)d0 * T_DIM + t0;
#pragma unroll
    for (int w = 0; w < 8; w++) {
        int idx = tid + w * 256;
        s[idx >> 5][idx & 31] = xp[(size_t)(idx >> 5) * T_DIM + (idx & 31)];
    }
    __syncthreads();
#pragma unroll
    for (int w = 0; w < 4; w++) {
        int idx = tid + w * 256;
        int dp = idx & 31, tt = idx >> 5;
        int m = n * T_DIM + t0 + tt;
        size_t o = (size_t)m * 256 + (d0 >> 1) + dp;
        float v0 = s[2 * dp][tt];
        float v1 = s[2 * dp + 1][tt];
        __nv_bfloat162 p1, p2;
        {
            __nv_bfloat16 h1 = __float2bfloat16_rn(v0);
            p1.x = h1;
            p2.x = __float2bfloat16_rn(v0 - __bfloat162float(h1));
        }
        {
            __nv_bfloat16 h1 = __float2bfloat16_rn(v1);
            p1.y = h1;
            p2.y = __float2bfloat16_rn(v1 - __bfloat162float(h1));
        }
        ((__nv_bfloat162*)g_z1)[o] = p1;
        ((__nv_bfloat162*)g_z2)[o] = p2;
        float2 zf; zf.x = v0; zf.y = v1;
        *(float2*)(g_zt + (size_t)m * 512 + d0 + 2 * dp) = zf;
    }
}

__global__ void prep_e_kernel(const float* __restrict__ E) {
    int i = blockIdx.x * 256 + threadIdx.x;
    float v = E[i];
    __nv_bfloat16 h1 = __float2bfloat16_rn(v);
    g_e1[i] = h1;
    g_e2[i] = __float2bfloat16_rn(v - __bfloat162float(h1));
}

// ---------------------------------------------------------------------------
// zsq (also inits argmin keys) / esq
// ---------------------------------------------------------------------------
__global__ void zsq_kernel(const float* __restrict__ x) {
    int m = blockIdx.x * 256 + threadIdx.x;
    int n = m >> 10;
    int t = m & 1023;
    const float* xp = x + (size_t)n * C_DIM * T_DIM + t;
    float acc = 0.f;
#pragma unroll 8
    for (int d = 0; d < D_DIM; d++) {
        float v = xp[(size_t)d * T_DIM];
        acc += v * v;
    }
    g_zsq[m] = acc;
    g_key[m] = 0xFFFFFFFFFFFFFFFFull;
}

__global__ void esq_kernel(const float* __restrict__ E) {
    __shared__ float red[128];
    int code = blockIdx.x;
    const float* e = E + (size_t)code * D_DIM;
    float acc = 0.f;
    for (int d = threadIdx.x; d < D_DIM; d += 128) {
        float v = e[d];
        acc += v * v;
    }
    red[threadIdx.x] = acc;
    __syncthreads();
    for (int s = 64; s > 0; s >>= 1) {
        if (threadIdx.x < s) red[threadIdx.x] += red[threadIdx.x + s];
        __syncthreads();
    }
    if (threadIdx.x == 0) g_esq[code] = red[0];
}

// ---------------------------------------------------------------------------
// Distance GEMM via mma.sync (HMMA bf16) + approximate global argmin.
// BM=BN=128, BK=32, 4-stage cp.async, 8 warps (2x4), warp tile 64x32.
// K_ext = 3*512: products z1e1, z1e2, z2e1 (Ootomo 2-way split).
// ---------------------------------------------------------------------------
#define BM 128
#define BN 128
#define BK 32
#define ASTRIDE 80                         // 64B row + 16B pad (conflict-free)
#define STAGE_BYTES (2 * BM * ASTRIDE)     // A + B = 20480
#define NSTAGES 4
#define DYN_SMEM (NSTAGES * STAGE_BYTES)   // 81920
#define KITERS 48

__device__ __forceinline__ void load_stage(
    uint32_t sbase, int tid, int m0, int n0, int it,
    const __nv_bfloat16* A, const __nv_bfloat16* B)
{
    int k0 = (it & 15) * BK;
#pragma unroll
    for (int q = 0; q < 2; q++) {
        int ch = tid + q * 256;
        int row = ch >> 2, c = ch & 3;
        cp16(sbase + row * ASTRIDE + c * 16,
             A + (size_t)(m0 + row) * 512 + k0 + c * 8);
    }
#pragma unroll
    for (int q = 0; q < 2; q++) {
        int ch = tid + q * 256;
        int row = ch >> 2, c = ch & 3;
        cp16(sbase + BM * ASTRIDE + row * ASTRIDE + c * 16,
             B + (size_t)(n0 + row) * 512 + k0 + c * 8);
    }
    CP_COMMIT();
}

__global__ __launch_bounds__(256) void mma_dist_kernel(float* __restrict__ out) {
    extern __shared__ char sm[];
    uint32_t smb;
    asm("{ .reg .u64 t; cvta.to.shared.u64 t, %1; cvt.u32.u64 %0, t; }"
        : "=r"(smb) : "l"(sm));

    int tid = threadIdx.x, lane = tid & 31, wid = tid >> 5;
    int wm = wid >> 2, wn = wid & 3;
    int n0 = blockIdx.x * BN, m0 = blockIdx.y * BM;

    const __nv_bfloat16* Aseg[3] = {g_z1, g_z1, g_z2};
    const __nv_bfloat16* Bseg[3] = {g_e1, g_e2, g_e1};

    int t8 = lane >> 3, lr = lane & 7;
    uint32_t offA[4][2], offB[2][2];
#pragma unroll
    for (int mt = 0; mt < 4; mt++)
#pragma unroll
        for (int ks = 0; ks < 2; ks++) {
            int row = wm * 64 + mt * 16 + (t8 & 1) * 8 + lr;
            int col = ks * 16 + (t8 >> 1) * 8;
            offA[mt][ks] = row * ASTRIDE + col * 2;
        }
#pragma unroll
    for (int np = 0; np < 2; np++)
#pragma unroll
        for (int ks = 0; ks < 2; ks++) {
            int row = wn * 32 + np * 16 + (t8 >> 1) * 8 + lr;
            int col = ks * 16 + (t8 & 1) * 8;
            offB[np][ks] = BM * ASTRIDE + row * ASTRIDE + col * 2;
        }

    float acc[4][4][4];
#pragma unroll
    for (int i = 0; i < 4; i++)
#pragma unroll
        for (int j = 0; j < 4; j++)
#pragma unroll
            for (int q = 0; q < 4; q++) acc[i][j][q] = 0.f;

#pragma unroll
    for (int s = 0; s < NSTAGES - 1; s++)
        load_stage(smb + s * STAGE_BYTES, tid, m0, n0, s, Aseg[s >> 4], Bseg[s >> 4]);

    for (int it = 0; it < KITERS; it++) {
        CP_WAIT2();
        __syncthreads();
        uint32_t sbase = smb + (it & 3) * STAGE_BYTES;
#pragma unroll
        for (int ks = 0; ks < 2; ks++) {
            uint32_t a[4][4], b[4][2];
#pragma unroll
            for (int mt = 0; mt < 4; mt++)
                LDSM4(a[mt][0], a[mt][1], a[mt][2], a[mt][3], sbase + offA[mt][ks]);
#pragma unroll
            for (int np = 0; np < 2; np++)
                LDSM4(b[2 * np][0], b[2 * np][1], b[2 * np + 1][0], b[2 * np + 1][1],
                      sbase + offB[np][ks]);
#pragma unroll
            for (int mt = 0; mt < 4; mt++)
#pragma unroll
                for (int nt = 0; nt < 4; nt++)
                    mma16816(acc[mt][nt], a[mt], b[nt]);
        }
        int nx = it + NSTAGES - 1;
        if (nx < KITERS)
            load_stage(smb + (nx & 3) * STAGE_BYTES, tid, m0, n0, nx,
                       Aseg[nx >> 4], Bseg[nx >> 4]);
        else
            CP_COMMIT();
    }

    // ---------------- epilogue ----------------
    __syncthreads();
    unsigned long long* keyrow = (unsigned long long*)sm;   // [128][4]

#pragma unroll
    for (int mt = 0; mt < 4; mt++) {
#pragma unroll
        for (int half = 0; half < 2; half++) {
            int rl = wm * 64 + mt * 16 + half * 8 + (lane >> 2);
            int row = m0 + rl;
            float zr = g_zsq[row];
            float best = 3.4e38f;
            int bi = 0;
#pragma unroll
            for (int nt = 0; nt < 4; nt++) {
                int col = n0 + wn * 32 + nt * 8 + (lane & 3) * 2;
                float d0 = fmaf(-2.f, acc[mt][nt][half * 2 + 0], zr) + g_esq[col];
                float d1 = fmaf(-2.f, acc[mt][nt][half * 2 + 1], zr) + g_esq[col + 1];
                float2 st; st.x = d0; st.y = d1;
                *(float2*)(out + O_DIST + (size_t)row * K_CODES + col) = st;
                if (d0 < best) { best = d0; bi = col; }
                if (d1 < best) { best = d1; bi = col + 1; }
            }
            unsigned long long key =
                ((unsigned long long)__float_as_uint(best) << 32) | (unsigned)bi;
#pragma unroll
            for (int ofs = 1; ofs <= 2; ofs <<= 1) {
                unsigned long long o = __shfl_xor_sync(0xffffffffu, key, ofs);
                if (o < key) key = o;
            }
            if ((lane & 3) == 0) keyrow[rl * 4 + wn] = key;
        }
    }
    __syncthreads();
    if (tid < 128) {
        unsigned long long k0 = keyrow[tid * 4 + 0];
        unsigned long long k1 = keyrow[tid * 4 + 1];
        unsigned long long k2 = keyrow[tid * 4 + 2];
        unsigned long long k3 = keyrow[tid * 4 + 3];
        if (k1 < k0) k0 = k1;
        if (k2 < k0) k0 = k2;
        if (k3 < k0) k0 = k3;
        atomicMin(&g_key[m0 + tid], k0);
    }
}

// ---------------------------------------------------------------------------
// Fixup: re-evaluate all near-tie candidates per row, MIMICKING the reference
// arithmetic: dot in fp64 (error ~1e-8 << ref's fp32 dot error ~2e-6), then
// dist assembled with the SAME fp32 expression and operands as the reference:
//   d = fl32( fl32(zsq - 2*dotf) + esq )
// Comparison on the fp32-quantized d with ties -> lower index (= jnp.argmin).
// This reproduces quantized ties correctly (R4's exact-fp64 compare broke them).
// ---------------------------------------------------------------------------
#define FIX_EPS 4e-3f
#define MAXCAND 32

__global__ __launch_bounds__(256) void fixup_kernel(const float* __restrict__ E,
                                                    float* __restrict__ out) {
    __shared__ int s_cnt[8];
    __shared__ int s_cand[8][MAXCAND];
    int w = threadIdx.x >> 5, lane = threadIdx.x & 31;
    int m = blockIdx.x * 8 + w;
    if (lane == 0) s_cnt[w] = 0;
    __syncwarp();

    float bestA = __uint_as_float((unsigned)(g_key[m] >> 32));
    float thr = bestA + FIX_EPS;
    const float* drow = out + O_DIST + (size_t)m * K_CODES;
#pragma unroll 4
    for (int c = lane; c < K_CODES; c += 32) {
        if (drow[c] <= thr) {
            int p = atomicAdd(&s_cnt[w], 1);
            if (p < MAXCAND) s_cand[w][p] = c;
        }
    }
    __syncwarp();
    int ncand = min(s_cnt[w], MAXCAND);

    const float* zrow = g_zt + (size_t)m * 512;
    double zc[16];
#pragma unroll
    for (int q = 0; q < 16; q++) zc[q] = (double)zrow[lane + q * 32];

    float zsq_m = g_zsq[m];
    float bd = 3.4e38f;
    int bi = 0x7FFFFFFF;
    for (int j = 0; j < ncand; j++) {
        int c = s_cand[w][j];
        const float* e = E + (size_t)c * 512;
        double s = 0.0;
#pragma unroll
        for (int q = 0; q < 16; q++)
            s += zc[q] * (double)e[lane + q * 32];
#pragma unroll
        for (int ofs = 16; ofs > 0; ofs >>= 1)
            s += __shfl_xor_sync(0xffffffffu, s, ofs);
        // reference-mimicking fp32 assembly: (zsq - 2*dot) + esq
        float dotf = (float)s;
        float t1 = zsq_m - 2.0f * dotf;
        float d = t1 + g_esq[c];
        if (d < bd || (d == bd && c < bi)) { bd = d; bi = c; }
    }
    if (lane == 0) {
        g_k[m] = bi;
        out[O_K + m] = (float)bi;
    }
}

// ---------------------------------------------------------------------------
// Gather neighbors + z_q_st + loss partials
// ---------------------------------------------------------------------------
__global__ void gather_kernel(const float* __restrict__ x,
                              const float* __restrict__ E,
                              float* __restrict__ out)
{
    __shared__ float s[512][17];
    __shared__ int   s_code[16][5];
    __shared__ float s_mask[16][5];
    __shared__ float red[256];

    int tid = threadIdx.x;
    int lane = tid & 15;
    int dgrp = tid >> 4;
    int n = blockIdx.y;
    int t0 = blockIdx.x * 16;
    const float* xp = x + (size_t)n * C_DIM * T_DIM + t0;

    for (int d = dgrp; d < 512; d += 16)
        s[d][lane] = xp[(size_t)d * T_DIM + lane];

    if (tid < 16) {
        int m = n * T_DIM + t0 + tid;
        int kk = g_k[m];
        int k1 = kk >> 5, k2 = kk & 31;
        s_code[tid][0] = kk;                 s_mask[tid][0] = 1.f;
        s_code[tid][1] = (k1 + 1) * 32 + k2; s_mask[tid][1] = (k1 < 31) ? 1.f : 0.f;
        s_code[tid][2] = (k1 - 1) * 32 + k2; s_mask[tid][2] = (k1 > 0)  ? 1.f : 0.f;
        s_code[tid][3] = kk + 1;             s_mask[tid][3] = (k2 < 31) ? 1.f : 0.f;
        s_code[tid][4] = kk - 1;             s_mask[tid][4] = (k2 > 0)  ? 1.f : 0.f;
    }
    __syncthreads();

    float cacc = 0.f, sacc = 0.f;
    for (int t = 0; t < 16; t++) {
        int m = n * T_DIM + t0 + t;
        float* nbp = out + O_NB + (size_t)m * (5 * 512);
        int code0 = s_code[t][0];
#pragma unroll
        for (int pass = 0; pass < 2; pass++) {
            int d = tid + pass * 256;
            float ze = s[d][t];
            float zq = E[(size_t)code0 * 512 + d];
            nbp[d] = zq;
            float diff = zq - ze;
            cacc += diff * diff;
            sacc += diff * diff;
#pragma unroll
            for (int slot = 1; slot < 5; slot++) {
                float msk = s_mask[t][slot];
                float v = 0.f;
                if (msk != 0.f) v = E[(size_t)s_code[t][slot] * 512 + d];
                nbp[slot * 512 + d] = v;
                float dd = ze - v;
                sacc += dd * dd;
            }
            s[d][t] = zq;
        }
    }
    __syncthreads();

    for (int d = dgrp; d < 512; d += 16)
        out[O_ZQST + (size_t)n * C_DIM * T_DIM + (size_t)d * T_DIM + t0 + lane]
            = s[d][lane];

    red[tid] = cacc;
    __syncthreads();
    for (int sft = 128; sft > 0; sft >>= 1) {
        if (tid < sft) red[tid] += red[tid + sft];
        __syncthreads();
    }
    float cblock = red[0];
    __syncthreads();
    red[tid] = sacc;
    __syncthreads();
    for (int sft = 128; sft > 0; sft >>= 1) {
        if (tid < sft) red[tid] += red[tid + sft];
        __syncthreads();
    }
    if (tid == 0) {
        int bid = blockIdx.y * gridDim.x + blockIdx.x;
        g_cpart[bid] = cblock;
        g_spart[bid] = red[0];
    }
}

__global__ void loss_kernel(float* __restrict__ out) {
    __shared__ double rc[256], rs[256];
    int tid = threadIdx.x;
    double c = 0.0, s = 0.0;
    for (int i = tid; i < NUM_GATHER_BLOCKS; i += 256) {
        c += (double)g_cpart[i];
        s += (double)g_spart[i];
    }
    rc[tid] = c; rs[tid] = s;
    __syncthreads();
    for (int sft = 128; sft > 0; sft >>= 1) {
        if (tid < sft) { rc[tid] += rc[tid + sft]; rs[tid] += rs[tid + sft]; }
        __syncthreads();
    }
    if (tid == 0) {
        double MD = (double)M_ROWS * (double)D_DIM;
        out[O_COMMIT] = (float)(2.0 * rc[0] / MD);
        out[O_SOM]    = (float)(rs[0] / (MD * 5.0));
    }
}

// ---------------------------------------------------------------------------
extern "C" void kernel_launch(void* const* d_in, const int* in_sizes, int n_in,
                              void* d_out, int out_size) {
    const float* x = (const float*)d_in[0];
    const float* E = (const float*)d_in[1];
    float* out = (float*)d_out;

    static int init = 0;
    if (!init) {
        cudaFuncSetAttribute(mma_dist_kernel,
                             cudaFuncAttributeMaxDynamicSharedMemorySize, DYN_SMEM);
        init = 1;
    }

    dim3 gz(T_DIM / 32, C_DIM / 64, N_B);
    prep_z_kernel<<<gz, 256>>>(x);
    prep_e_kernel<<<(K_CODES * D_DIM) / 256, 256>>>(E);
    zsq_kernel<<<M_ROWS / 256, 256>>>(x);
    esq_kernel<<<K_CODES, 128>>>(E);
    dim3 gd(K_CODES / BN, M_ROWS / BM);
    mma_dist_kernel<<<gd, 256, DYN_SMEM>>>(out);
    fixup_kernel<<<M_ROWS / 8, 256>>>(E, out);
    dim3 g(T_DIM / 16, N_B);
    gather_kernel<<<g, 256>>>(x, E, out);
    loss_kernel<<<1, 256>>>(out);
}

// round 6
// speedup vs baseline: 2.4256x; 1.3146x over previous
#include <cuda_runtime.h>
#include <cuda_bf16.h>
#include <cstdint>

// Problem constants
#define N_B    32
#define C_DIM  512
#define T_DIM  1024
#define D_DIM  512
#define K_CODES 1024
#define M_ROWS 32768

// Output layout (concatenation of reference return tuple, fp32)
#define O_ZQST   0UL
#define O_COMMIT 16777216UL
#define O_SOM    16777217UL
#define O_NB     16777218UL
#define O_DIST   100663298UL
#define O_K      134217730UL

#define NUM_GATHER_BLOCKS 2048

// ---------------- scratch (device globals; no allocations) ----------------
static __device__ float g_zsq[M_ROWS];
static __device__ float g_esq[K_CODES];
static __device__ int   g_k[M_ROWS];
static __device__ unsigned long long g_key[M_ROWS];
static __device__ float g_cpart[NUM_GATHER_BLOCKS];
static __device__ float g_spart[NUM_GATHER_BLOCKS];

// bf16 operands + contiguous fp32 transposed z (for exact fixup)
static __device__ __nv_bfloat16 g_z1[M_ROWS * D_DIM];
static __device__ __nv_bfloat16 g_e1[K_CODES * D_DIM];
static __device__ float g_zt[M_ROWS * D_DIM];

// ---------------- PTX helpers (baseline sm_80+ PTX, valid on compute_103) ----
__device__ __forceinline__ void cp16(uint32_t dst, const void* src) {
    asm volatile("cp.async.cg.shared.global [%0], [%1], 16;" :: "r"(dst), "l"(src));
}
#define CP_COMMIT() asm volatile("cp.async.commit_group;" ::: "memory")
#define CP_WAIT2()  asm volatile("cp.async.wait_group 2;" ::: "memory")

#define LDSM4(r0, r1, r2, r3, addr)                                        \
    asm volatile("ldmatrix.sync.aligned.m8n8.x4.shared.b16 {%0,%1,%2,%3}, [%4];" \
                 : "=r"(r0), "=r"(r1), "=r"(r2), "=r"(r3) : "r"(addr))

__device__ __forceinline__ void mma16816(float* c, const uint32_t* a, const uint32_t* b) {
    asm volatile(
        "mma.sync.aligned.m16n8k16.row.col.f32.bf16.bf16.f32 "
        "{%0,%1,%2,%3}, {%4,%5,%6,%7}, {%8,%9}, {%0,%1,%2,%3};"
        : "+f"(c[0]), "+f"(c[1]), "+f"(c[2]), "+f"(c[3])
        : "r"(a[0]), "r"(a[1]), "r"(a[2]), "r"(a[3]), "r"(b[0]), "r"(b[1]));
}

// ---------------------------------------------------------------------------
// Prep: transpose x -> z rows (m-major), bf16 + fp32 copies
// ---------------------------------------------------------------------------
__global__ void prep_z_kernel(const float* __restrict__ x) {
    __shared__ float s[64][33];
    int tid = threadIdx.x;
    int t0 = blockIdx.x * 32, d0 = blockIdx.y * 64, n = blockIdx.z;
    const float* xp = x + (size_t)n * C_DIM * T_DIM + (size_t)d0 * T_DIM + t0;
#pragma unroll
    for (int w = 0; w < 8; w++) {
        int idx = tid + w * 256;
        s[idx >> 5][idx & 31] = xp[(size_t)(idx >> 5) * T_DIM + (idx & 31)];
    }
    __syncthreads();
#pragma unroll
    for (int w = 0; w < 4; w++) {
        int idx = tid + w * 256;
        int dp = idx & 31, tt = idx >> 5;
        int m = n * T_DIM + t0 + tt;
        size_t o = (size_t)m * 256 + (d0 >> 1) + dp;
        float v0 = s[2 * dp][tt];
        float v1 = s[2 * dp + 1][tt];
        __nv_bfloat162 p1;
        p1.x = __float2bfloat16_rn(v0);
        p1.y = __float2bfloat16_rn(v1);
        ((__nv_bfloat162*)g_z1)[o] = p1;
        float2 zf; zf.x = v0; zf.y = v1;
        *(float2*)(g_zt + (size_t)m * 512 + d0 + 2 * dp) = zf;
    }
}

__global__ void prep_e_kernel(const float* __restrict__ E) {
    int i = blockIdx.x * 256 + threadIdx.x;
    g_e1[i] = __float2bfloat16_rn(E[i]);
}

// ---------------------------------------------------------------------------
// zsq (also inits argmin keys) / esq
// ---------------------------------------------------------------------------
__global__ void zsq_kernel(const float* __restrict__ x) {
    int m = blockIdx.x * 256 + threadIdx.x;
    int n = m >> 10;
    int t = m & 1023;
    const float* xp = x + (size_t)n * C_DIM * T_DIM + t;
    float acc = 0.f;
#pragma unroll 8
    for (int d = 0; d < D_DIM; d++) {
        float v = xp[(size_t)d * T_DIM];
        acc += v * v;
    }
    g_zsq[m] = acc;
    g_key[m] = 0xFFFFFFFFFFFFFFFFull;
}

__global__ void esq_kernel(const float* __restrict__ E) {
    __shared__ float red[128];
    int code = blockIdx.x;
    const float* e = E + (size_t)code * D_DIM;
    float acc = 0.f;
    for (int d = threadIdx.x; d < D_DIM; d += 128) {
        float v = e[d];
        acc += v * v;
    }
    red[threadIdx.x] = acc;
    __syncthreads();
    for (int s = 64; s > 0; s >>= 1) {
        if (threadIdx.x < s) red[threadIdx.x] += red[threadIdx.x + s];
        __syncthreads();
    }
    if (threadIdx.x == 0) g_esq[code] = red[0];
}

// ---------------------------------------------------------------------------
// Distance GEMM via mma.sync (HMMA bf16) + approximate global argmin.
// BM=BN=128, BK=32, 4-stage cp.async, 8 warps (2x4), warp tile 64x32.
// Single bf16 product (fixup pass restores exact argmin; dist output err ~1e-5).
// ---------------------------------------------------------------------------
#define BM 128
#define BN 128
#define BK 32
#define ASTRIDE 80                         // 64B row + 16B pad (conflict-free)
#define STAGE_BYTES (2 * BM * ASTRIDE)     // A + B = 20480
#define NSTAGES 4
#define DYN_SMEM (NSTAGES * STAGE_BYTES)   // 81920 (2 CTAs/SM: 160KB <= 227KB)
#define KITERS 16

__device__ __forceinline__ void load_stage(
    uint32_t sbase, int tid, int m0, int n0, int it)
{
    int k0 = it * BK;
#pragma unroll
    for (int q = 0; q < 2; q++) {
        int ch = tid + q * 256;
        int row = ch >> 2, c = ch & 3;
        cp16(sbase + row * ASTRIDE + c * 16,
             g_z1 + (size_t)(m0 + row) * 512 + k0 + c * 8);
    }
#pragma unroll
    for (int q = 0; q < 2; q++) {
        int ch = tid + q * 256;
        int row = ch >> 2, c = ch & 3;
        cp16(sbase + BM * ASTRIDE + row * ASTRIDE + c * 16,
             g_e1 + (size_t)(n0 + row) * 512 + k0 + c * 8);
    }
    CP_COMMIT();
}

__global__ __launch_bounds__(256, 2) void mma_dist_kernel(float* __restrict__ out) {
    extern __shared__ char sm[];
    uint32_t smb;
    asm("{ .reg .u64 t; cvta.to.shared.u64 t, %1; cvt.u32.u64 %0, t; }"
        : "=r"(smb) : "l"(sm));

    int tid = threadIdx.x, lane = tid & 31, wid = tid >> 5;
    int wm = wid >> 2, wn = wid & 3;
    int n0 = blockIdx.x * BN, m0 = blockIdx.y * BM;

    int t8 = lane >> 3, lr = lane & 7;
    uint32_t offA[4][2], offB[2][2];
#pragma unroll
    for (int mt = 0; mt < 4; mt++)
#pragma unroll
        for (int ks = 0; ks < 2; ks++) {
            int row = wm * 64 + mt * 16 + (t8 & 1) * 8 + lr;
            int col = ks * 16 + (t8 >> 1) * 8;
            offA[mt][ks] = row * ASTRIDE + col * 2;
        }
#pragma unroll
    for (int np = 0; np < 2; np++)
#pragma unroll
        for (int ks = 0; ks < 2; ks++) {
            int row = wn * 32 + np * 16 + (t8 >> 1) * 8 + lr;
            int col = ks * 16 + (t8 & 1) * 8;
            offB[np][ks] = BM * ASTRIDE + row * ASTRIDE + col * 2;
        }

    float acc[4][4][4];
#pragma unroll
    for (int i = 0; i < 4; i++)
#pragma unroll
        for (int j = 0; j < 4; j++)
#pragma unroll
            for (int q = 0; q < 4; q++) acc[i][j][q] = 0.f;

#pragma unroll
    for (int s = 0; s < NSTAGES - 1; s++)
        load_stage(smb + s * STAGE_BYTES, tid, m0, n0, s);

    for (int it = 0; it < KITERS; it++) {
        CP_WAIT2();
        __syncthreads();
        uint32_t sbase = smb + (it & 3) * STAGE_BYTES;
#pragma unroll
        for (int ks = 0; ks < 2; ks++) {
            uint32_t a[4][4], b[4][2];
#pragma unroll
            for (int mt = 0; mt < 4; mt++)
                LDSM4(a[mt][0], a[mt][1], a[mt][2], a[mt][3], sbase + offA[mt][ks]);
#pragma unroll
            for (int np = 0; np < 2; np++)
                LDSM4(b[2 * np][0], b[2 * np][1], b[2 * np + 1][0], b[2 * np + 1][1],
                      sbase + offB[np][ks]);
#pragma unroll
            for (int mt = 0; mt < 4; mt++)
#pragma unroll
                for (int nt = 0; nt < 4; nt++)
                    mma16816(acc[mt][nt], a[mt], b[nt]);
        }
        int nx = it + NSTAGES - 1;
        if (nx < KITERS)
            load_stage(smb + (nx & 3) * STAGE_BYTES, tid, m0, n0, nx);
        else
            CP_COMMIT();
    }

    // ---------------- epilogue ----------------
    __syncthreads();
    unsigned long long* keyrow = (unsigned long long*)sm;   // [128][4]

#pragma unroll
    for (int mt = 0; mt < 4; mt++) {
#pragma unroll
        for (int half = 0; half < 2; half++) {
            int rl = wm * 64 + mt * 16 + half * 8 + (lane >> 2);
            int row = m0 + rl;
            float zr = g_zsq[row];
            float best = 3.4e38f;
            int bi = 0;
#pragma unroll
            for (int nt = 0; nt < 4; nt++) {
                int col = n0 + wn * 32 + nt * 8 + (lane & 3) * 2;
                float d0 = fmaf(-2.f, acc[mt][nt][half * 2 + 0], zr) + g_esq[col];
                float d1 = fmaf(-2.f, acc[mt][nt][half * 2 + 1], zr) + g_esq[col + 1];
                float2 st; st.x = d0; st.y = d1;
                *(float2*)(out + O_DIST + (size_t)row * K_CODES + col) = st;
                if (d0 < best) { best = d0; bi = col; }
                if (d1 < best) { best = d1; bi = col + 1; }
            }
            unsigned long long key =
                ((unsigned long long)__float_as_uint(best) << 32) | (unsigned)bi;
#pragma unroll
            for (int ofs = 1; ofs <= 2; ofs <<= 1) {
                unsigned long long o = __shfl_xor_sync(0xffffffffu, key, ofs);
                if (o < key) key = o;
            }
            if ((lane & 3) == 0) keyrow[rl * 4 + wn] = key;
        }
    }
    __syncthreads();
    if (tid < 128) {
        unsigned long long k0 = keyrow[tid * 4 + 0];
        unsigned long long k1 = keyrow[tid * 4 + 1];
        unsigned long long k2 = keyrow[tid * 4 + 2];
        unsigned long long k3 = keyrow[tid * 4 + 3];
        if (k1 < k0) k0 = k1;
        if (k2 < k0) k0 = k2;
        if (k3 < k0) k0 = k3;
        atomicMin(&g_key[m0 + tid], k0);
    }
}

// ---------------------------------------------------------------------------
// Fixup: re-evaluate near-tie candidates mimicking reference arithmetic:
// fp64 dot, then d = fl32( fl32(zsq - 2*dotf) + esq ); ties -> lower index.
// EPS = 0.1 (~20 sigma of the bf16 GEMM distance error).
// ---------------------------------------------------------------------------
#define FIX_EPS 0.1f
#define MAXCAND 64

__global__ __launch_bounds__(256) void fixup_kernel(const float* __restrict__ E,
                                                    float* __restrict__ out) {
    __shared__ int s_cnt[8];
    __shared__ int s_cand[8][MAXCAND];
    int w = threadIdx.x >> 5, lane = threadIdx.x & 31;
    int m = blockIdx.x * 8 + w;
    if (lane == 0) s_cnt[w] = 0;
    __syncwarp();

    float bestA = __uint_as_float((unsigned)(g_key[m] >> 32));
    float thr = bestA + FIX_EPS;
    const float* drow = out + O_DIST + (size_t)m * K_CODES;
#pragma unroll 4
    for (int c = lane; c < K_CODES; c += 32) {
        if (drow[c] <= thr) {
            int p = atomicAdd(&s_cnt[w], 1);
            if (p < MAXCAND) s_cand[w][p] = c;
        }
    }
    __syncwarp();
    int ncand = min(s_cnt[w], MAXCAND);

    const float* zrow = g_zt + (size_t)m * 512;
    double zc[16];
#pragma unroll
    for (int q = 0; q < 16; q++) zc[q] = (double)zrow[lane + q * 32];

    float zsq_m = g_zsq[m];
    float bd = 3.4e38f;
    int bi = 0x7FFFFFFF;
    for (int j = 0; j < ncand; j++) {
        int c = s_cand[w][j];
        const float* e = E + (size_t)c * 512;
        double s = 0.0;
#pragma unroll
        for (int q = 0; q < 16; q++)
            s += zc[q] * (double)e[lane + q * 32];
#pragma unroll
        for (int ofs = 16; ofs > 0; ofs >>= 1)
            s += __shfl_xor_sync(0xffffffffu, s, ofs);
        float dotf = (float)s;
        float t1 = zsq_m - 2.0f * dotf;
        float d = t1 + g_esq[c];
        if (d < bd || (d == bd && c < bi)) { bd = d; bi = c; }
    }
    if (lane == 0) {
        g_k[m] = bi;
        out[O_K + m] = (float)bi;
    }
}

// ---------------------------------------------------------------------------
// Gather neighbors + z_q_st + loss partials (streaming stores for
// write-once outputs so E stays hot in L2)
// ---------------------------------------------------------------------------
__global__ void gather_kernel(const float* __restrict__ x,
                              const float* __restrict__ E,
                              float* __restrict__ out)
{
    __shared__ float s[512][17];
    __shared__ int   s_code[16][5];
    __shared__ float s_mask[16][5];
    __shared__ float red[256];

    int tid = threadIdx.x;
    int lane = tid & 15;
    int dgrp = tid >> 4;
    int n = blockIdx.y;
    int t0 = blockIdx.x * 16;
    const float* xp = x + (size_t)n * C_DIM * T_DIM + t0;

    for (int d = dgrp; d < 512; d += 16)
        s[d][lane] = xp[(size_t)d * T_DIM + lane];

    if (tid < 16) {
        int m = n * T_DIM + t0 + tid;
        int kk = g_k[m];
        int k1 = kk >> 5, k2 = kk & 31;
        s_code[tid][0] = kk;                 s_mask[tid][0] = 1.f;
        s_code[tid][1] = (k1 + 1) * 32 + k2; s_mask[tid][1] = (k1 < 31) ? 1.f : 0.f;
        s_code[tid][2] = (k1 - 1) * 32 + k2; s_mask[tid][2] = (k1 > 0)  ? 1.f : 0.f;
        s_code[tid][3] = kk + 1;             s_mask[tid][3] = (k2 < 31) ? 1.f : 0.f;
        s_code[tid][4] = kk - 1;             s_mask[tid][4] = (k2 > 0)  ? 1.f : 0.f;
    }
    __syncthreads();

    float cacc = 0.f, sacc = 0.f;
    for (int t = 0; t < 16; t++) {
        int m = n * T_DIM + t0 + t;
        float* nbp = out + O_NB + (size_t)m * (5 * 512);
        int code0 = s_code[t][0];
#pragma unroll
        for (int pass = 0; pass < 2; pass++) {
            int d = tid + pass * 256;
            float ze = s[d][t];
            float zq = E[(size_t)code0 * 512 + d];
            __stcs(&nbp[d], zq);
            float diff = zq - ze;
            cacc += diff * diff;
            sacc += diff * diff;
#pragma unroll
            for (int slot = 1; slot < 5; slot++) {
                float msk = s_mask[t][slot];
                float v = 0.f;
                if (msk != 0.f) v = E[(size_t)s_code[t][slot] * 512 + d];
                __stcs(&nbp[slot * 512 + d], v);
                float dd = ze - v;
                sacc += dd * dd;
            }
            s[d][t] = zq;
        }
    }
    __syncthreads();

    for (int d = dgrp; d < 512; d += 16)
        __stcs(&out[O_ZQST + (size_t)n * C_DIM * T_DIM + (size_t)d * T_DIM + t0 + lane],
               s[d][lane]);

    red[tid] = cacc;
    __syncthreads();
    for (int sft = 128; sft > 0; sft >>= 1) {
        if (tid < sft) red[tid] += red[tid + sft];
        __syncthreads();
    }
    float cblock = red[0];
    __syncthreads();
    red[tid] = sacc;
    __syncthreads();
    for (int sft = 128; sft > 0; sft >>= 1) {
        if (tid < sft) red[tid] += red[tid + sft];
        __syncthreads();
    }
    if (tid == 0) {
        int bid = blockIdx.y * gridDim.x + blockIdx.x;
        g_cpart[bid] = cblock;
        g_spart[bid] = red[0];
    }
}

__global__ void loss_kernel(float* __restrict__ out) {
    __shared__ double rc[256], rs[256];
    int tid = threadIdx.x;
    double c = 0.0, s = 0.0;
    for (int i = tid; i < NUM_GATHER_BLOCKS; i += 256) {
        c += (double)g_cpart[i];
        s += (double)g_spart[i];
    }
    rc[tid] = c; rs[tid] = s;
    __syncthreads();
    for (int sft = 128; sft > 0; sft >>= 1) {
        if (tid < sft) { rc[tid] += rc[tid + sft]; rs[tid] += rs[tid + sft]; }
        __syncthreads();
    }
    if (tid == 0) {
        double MD = (double)M_ROWS * (double)D_DIM;
        out[O_COMMIT] = (float)(2.0 * rc[0] / MD);
        out[O_SOM]    = (float)(rs[0] / (MD * 5.0));
    }
}

// ---------------------------------------------------------------------------
extern "C" void kernel_launch(void* const* d_in, const int* in_sizes, int n_in,
                              void* d_out, int out_size) {
    const float* x = (const float*)d_in[0];
    const float* E = (const float*)d_in[1];
    float* out = (float*)d_out;

    static int init = 0;
    if (!init) {
        cudaFuncSetAttribute(mma_dist_kernel,
                             cudaFuncAttributeMaxDynamicSharedMemorySize, DYN_SMEM);
        init = 1;
    }

    dim3 gz(T_DIM / 32, C_DIM / 64, N_B);
    prep_z_kernel<<<gz, 256>>>(x);
    prep_e_kernel<<<(K_CODES * D_DIM) / 256, 256>>>(E);
    zsq_kernel<<<M_ROWS / 256, 256>>>(x);
    esq_kernel<<<K_CODES, 128>>>(E);
    dim3 gd(K_CODES / BN, M_ROWS / BM);
    mma_dist_kernel<<<gd, 256, DYN_SMEM>>>(out);
    fixup_kernel<<<M_ROWS / 8, 256>>>(E, out);
    dim3 g(T_DIM / 16, N_B);
    gather_kernel<<<g, 256>>>(x, E, out);
    loss_kernel<<<1, 256>>>(out);
}

// round 7
// speedup vs baseline: 3.3114x; 1.3652x over previous
#include <cuda_runtime.h>
#include <cuda_bf16.h>
#include <cstdint>

// Problem constants
#define N_B    32
#define C_DIM  512
#define T_DIM  1024
#define D_DIM  512
#define K_CODES 1024
#define M_ROWS 32768

// Output layout (concatenation of reference return tuple, fp32)
#define O_ZQST   0UL
#define O_COMMIT 16777216UL
#define O_SOM    16777217UL
#define O_NB     16777218UL
#define O_DIST   100663298UL
#define O_K      134217730UL

#define NUM_GATHER_BLOCKS 1024    // 32 n * 32 t-tiles

// ---------------- scratch (device globals; no allocations) ----------------
static __device__ float g_zsq[M_ROWS];
static __device__ float g_zsqp[8][M_ROWS];
static __device__ float g_esq[K_CODES];
static __device__ int   g_k[M_ROWS];
static __device__ unsigned long long g_key[M_ROWS];
static __device__ float g_cpart[NUM_GATHER_BLOCKS];
static __device__ float g_spart[NUM_GATHER_BLOCKS];

// bf16 operands + contiguous fp32 transposed z (for exact fixup)
static __device__ __nv_bfloat16 g_z1[M_ROWS * D_DIM];
static __device__ __nv_bfloat16 g_e1[K_CODES * D_DIM];
static __device__ float g_zt[M_ROWS * D_DIM];

// ---------------- PTX helpers (baseline sm_80+ PTX, valid on compute_103) ----
__device__ __forceinline__ void cp16(uint32_t dst, const void* src) {
    asm volatile("cp.async.cg.shared.global [%0], [%1], 16;" :: "r"(dst), "l"(src));
}
#define CP_COMMIT() asm volatile("cp.async.commit_group;" ::: "memory")
#define CP_WAIT2()  asm volatile("cp.async.wait_group 2;" ::: "memory")

#define LDSM4(r0, r1, r2, r3, addr)                                        \
    asm volatile("ldmatrix.sync.aligned.m8n8.x4.shared.b16 {%0,%1,%2,%3}, [%4];" \
                 : "=r"(r0), "=r"(r1), "=r"(r2), "=r"(r3) : "r"(addr))

__device__ __forceinline__ void mma16816(float* c, const uint32_t* a, const uint32_t* b) {
    asm volatile(
        "mma.sync.aligned.m16n8k16.row.col.f32.bf16.bf16.f32 "
        "{%0,%1,%2,%3}, {%4,%5,%6,%7}, {%8,%9}, {%0,%1,%2,%3};"
        : "+f"(c[0]), "+f"(c[1]), "+f"(c[2]), "+f"(c[3])
        : "r"(a[0]), "r"(a[1]), "r"(a[2]), "r"(a[3]), "r"(b[0]), "r"(b[1]));
}

// ---------------------------------------------------------------------------
// Prep: transpose x -> z rows (m-major), bf16 + fp32 copies + zsq partials
// ---------------------------------------------------------------------------
__global__ void prep_z_kernel(const float* __restrict__ x) {
    __shared__ float s[64][33];
    int tid = threadIdx.x;
    int t0 = blockIdx.x * 32, d0 = blockIdx.y * 64, n = blockIdx.z;
    const float* xp = x + (size_t)n * C_DIM * T_DIM + (size_t)d0 * T_DIM + t0;
#pragma unroll
    for (int w = 0; w < 8; w++) {
        int idx = tid + w * 256;
        s[idx >> 5][idx & 31] = xp[(size_t)(idx >> 5) * T_DIM + (idx & 31)];
    }
    __syncthreads();
#pragma unroll
    for (int w = 0; w < 4; w++) {
        int idx = tid + w * 256;
        int dp = idx & 31, tt = idx >> 5;
        int m = n * T_DIM + t0 + tt;
        size_t o = (size_t)m * 256 + (d0 >> 1) + dp;
        float v0 = s[2 * dp][tt];
        float v1 = s[2 * dp + 1][tt];
        __nv_bfloat162 p1;
        p1.x = __float2bfloat16_rn(v0);
        p1.y = __float2bfloat16_rn(v1);
        ((__nv_bfloat162*)g_z1)[o] = p1;
        float2 zf; zf.x = v0; zf.y = v1;
        *(float2*)(g_zt + (size_t)m * 512 + d0 + 2 * dp) = zf;
    }
    // zsq partial for this 64-d block (threads 0..31, one t each)
    if (tid < 32) {
        float acc = 0.f;
#pragma unroll
        for (int d = 0; d < 64; d++) {
            float v = s[d][tid];
            acc += v * v;
        }
        g_zsqp[d0 >> 6][n * T_DIM + t0 + tid] = acc;
    }
}

__global__ void zsq_combine_kernel() {
    int m = blockIdx.x * 256 + threadIdx.x;
    float acc = 0.f;
#pragma unroll
    for (int q = 0; q < 8; q++) acc += g_zsqp[q][m];
    g_zsq[m] = acc;
    g_key[m] = 0xFFFFFFFFFFFFFFFFull;
}

__global__ void prep_e_kernel(const float* __restrict__ E) {
    int i = blockIdx.x * 256 + threadIdx.x;
    g_e1[i] = __float2bfloat16_rn(E[i]);
}

__global__ void esq_kernel(const float* __restrict__ E) {
    __shared__ float red[128];
    int code = blockIdx.x;
    const float* e = E + (size_t)code * D_DIM;
    float acc = 0.f;
    for (int d = threadIdx.x; d < D_DIM; d += 128) {
        float v = e[d];
        acc += v * v;
    }
    red[threadIdx.x] = acc;
    __syncthreads();
    for (int s = 64; s > 0; s >>= 1) {
        if (threadIdx.x < s) red[threadIdx.x] += red[threadIdx.x + s];
        __syncthreads();
    }
    if (threadIdx.x == 0) g_esq[code] = red[0];
}

// ---------------------------------------------------------------------------
// Distance GEMM via mma.sync (HMMA bf16) + approximate global argmin.
// ---------------------------------------------------------------------------
#define BM 128
#define BN 128
#define BK 32
#define ASTRIDE 80
#define STAGE_BYTES (2 * BM * ASTRIDE)
#define NSTAGES 4
#define DYN_SMEM (NSTAGES * STAGE_BYTES)
#define KITERS 16

__device__ __forceinline__ void load_stage(
    uint32_t sbase, int tid, int m0, int n0, int it)
{
    int k0 = it * BK;
#pragma unroll
    for (int q = 0; q < 2; q++) {
        int ch = tid + q * 256;
        int row = ch >> 2, c = ch & 3;
        cp16(sbase + row * ASTRIDE + c * 16,
             g_z1 + (size_t)(m0 + row) * 512 + k0 + c * 8);
    }
#pragma unroll
    for (int q = 0; q < 2; q++) {
        int ch = tid + q * 256;
        int row = ch >> 2, c = ch & 3;
        cp16(sbase + BM * ASTRIDE + row * ASTRIDE + c * 16,
             g_e1 + (size_t)(n0 + row) * 512 + k0 + c * 8);
    }
    CP_COMMIT();
}

__global__ __launch_bounds__(256, 2) void mma_dist_kernel(float* __restrict__ out) {
    extern __shared__ char sm[];
    uint32_t smb;
    asm("{ .reg .u64 t; cvta.to.shared.u64 t, %1; cvt.u32.u64 %0, t; }"
        : "=r"(smb) : "l"(sm));

    int tid = threadIdx.x, lane = tid & 31, wid = tid >> 5;
    int wm = wid >> 2, wn = wid & 3;
    int n0 = blockIdx.x * BN, m0 = blockIdx.y * BM;

    int t8 = lane >> 3, lr = lane & 7;
    uint32_t offA[4][2], offB[2][2];
#pragma unroll
    for (int mt = 0; mt < 4; mt++)
#pragma unroll
        for (int ks = 0; ks < 2; ks++) {
            int row = wm * 64 + mt * 16 + (t8 & 1) * 8 + lr;
            int col = ks * 16 + (t8 >> 1) * 8;
            offA[mt][ks] = row * ASTRIDE + col * 2;
        }
#pragma unroll
    for (int np = 0; np < 2; np++)
#pragma unroll
        for (int ks = 0; ks < 2; ks++) {
            int row = wn * 32 + np * 16 + (t8 >> 1) * 8 + lr;
            int col = ks * 16 + (t8 & 1) * 8;
            offB[np][ks] = BM * ASTRIDE + row * ASTRIDE + col * 2;
        }

    float acc[4][4][4];
#pragma unroll
    for (int i = 0; i < 4; i++)
#pragma unroll
        for (int j = 0; j < 4; j++)
#pragma unroll
            for (int q = 0; q < 4; q++) acc[i][j][q] = 0.f;

#pragma unroll
    for (int s = 0; s < NSTAGES - 1; s++)
        load_stage(smb + s * STAGE_BYTES, tid, m0, n0, s);

    for (int it = 0; it < KITERS; it++) {
        CP_WAIT2();
        __syncthreads();
        uint32_t sbase = smb + (it & 3) * STAGE_BYTES;
#pragma unroll
        for (int ks = 0; ks < 2; ks++) {
            uint32_t a[4][4], b[4][2];
#pragma unroll
            for (int mt = 0; mt < 4; mt++)
                LDSM4(a[mt][0], a[mt][1], a[mt][2], a[mt][3], sbase + offA[mt][ks]);
#pragma unroll
            for (int np = 0; np < 2; np++)
                LDSM4(b[2 * np][0], b[2 * np][1], b[2 * np + 1][0], b[2 * np + 1][1],
                      sbase + offB[np][ks]);
#pragma unroll
            for (int mt = 0; mt < 4; mt++)
#pragma unroll
                for (int nt = 0; nt < 4; nt++)
                    mma16816(acc[mt][nt], a[mt], b[nt]);
        }
        int nx = it + NSTAGES - 1;
        if (nx < KITERS)
            load_stage(smb + (nx & 3) * STAGE_BYTES, tid, m0, n0, nx);
        else
            CP_COMMIT();
    }

    // ---------------- epilogue ----------------
    __syncthreads();
    unsigned long long* keyrow = (unsigned long long*)sm;   // [128][4]

#pragma unroll
    for (int mt = 0; mt < 4; mt++) {
#pragma unroll
        for (int half = 0; half < 2; half++) {
            int rl = wm * 64 + mt * 16 + half * 8 + (lane >> 2);
            int row = m0 + rl;
            float zr = g_zsq[row];
            float best = 3.4e38f;
            int bi = 0;
#pragma unroll
            for (int nt = 0; nt < 4; nt++) {
                int col = n0 + wn * 32 + nt * 8 + (lane & 3) * 2;
                float d0 = fmaf(-2.f, acc[mt][nt][half * 2 + 0], zr) + g_esq[col];
                float d1 = fmaf(-2.f, acc[mt][nt][half * 2 + 1], zr) + g_esq[col + 1];
                float2 st; st.x = d0; st.y = d1;
                __stcs((float2*)(out + O_DIST + (size_t)row * K_CODES + col), st);
                if (d0 < best) { best = d0; bi = col; }
                if (d1 < best) { best = d1; bi = col + 1; }
            }
            unsigned long long key =
                ((unsigned long long)__float_as_uint(best) << 32) | (unsigned)bi;
#pragma unroll
            for (int ofs = 1; ofs <= 2; ofs <<= 1) {
                unsigned long long o = __shfl_xor_sync(0xffffffffu, key, ofs);
                if (o < key) key = o;
            }
            if ((lane & 3) == 0) keyrow[rl * 4 + wn] = key;
        }
    }
    __syncthreads();
    if (tid < 128) {
        unsigned long long k0 = keyrow[tid * 4 + 0];
        unsigned long long k1 = keyrow[tid * 4 + 1];
        unsigned long long k2 = keyrow[tid * 4 + 2];
        unsigned long long k3 = keyrow[tid * 4 + 3];
        if (k1 < k0) k0 = k1;
        if (k2 < k0) k0 = k2;
        if (k3 < k0) k0 = k3;
        atomicMin(&g_key[m0 + tid], k0);
    }
}

// ---------------------------------------------------------------------------
// Fixup: lazy near-tie re-evaluation. If only one candidate within EPS it IS
// the argmin (skip all loads). Otherwise fp64 dot + reference-mimicking fp32
// assembly: d = fl32( fl32(zsq - 2*dotf) + esq ); ties -> lower index.
// ---------------------------------------------------------------------------
#define FIX_EPS 0.1f
#define MAXCAND 64

__global__ __launch_bounds__(256) void fixup_kernel(const float* __restrict__ E,
                                                    float* __restrict__ out) {
    __shared__ int s_cnt[8];
    __shared__ int s_cand[8][MAXCAND];
    int w = threadIdx.x >> 5, lane = threadIdx.x & 31;
    int m = blockIdx.x * 8 + w;
    if (lane == 0) s_cnt[w] = 0;
    __syncwarp();

    unsigned long long gk = g_key[m];
    float bestA = __uint_as_float((unsigned)(gk >> 32));
    float thr = bestA + FIX_EPS;
    const float* drow = out + O_DIST + (size_t)m * K_CODES;
#pragma unroll 4
    for (int c = lane; c < K_CODES; c += 32) {
        if (__ldcs(&drow[c]) <= thr) {
            int p = atomicAdd(&s_cnt[w], 1);
            if (p < MAXCAND) s_cand[w][p] = c;
        }
    }
    __syncwarp();
    int ncand = min(s_cnt[w], MAXCAND);

    int bi;
    if (ncand == 1) {
        bi = s_cand[w][0];                 // the global min itself
    } else {
        const float* zrow = g_zt + (size_t)m * 512;
        double zc[16];
#pragma unroll
        for (int q = 0; q < 16; q++) zc[q] = (double)zrow[lane + q * 32];
        float zsq_m = g_zsq[m];
        float bd = 3.4e38f;
        bi = 0x7FFFFFFF;
        for (int j = 0; j < ncand; j++) {
            int c = s_cand[w][j];
            const float* e = E + (size_t)c * 512;
            double s = 0.0;
#pragma unroll
            for (int q = 0; q < 16; q++)
                s += zc[q] * (double)e[lane + q * 32];
#pragma unroll
            for (int ofs = 16; ofs > 0; ofs >>= 1)
                s += __shfl_xor_sync(0xffffffffu, s, ofs);
            float dotf = (float)s;
            float t1 = zsq_m - 2.0f * dotf;
            float d = t1 + g_esq[c];
            if (d < bd || (d == bd && c < bi)) { bd = d; bi = c; }
        }
    }
    if (lane == 0) {
        g_k[m] = bi;
        out[O_K + m] = (float)bi;
    }
}

// ---------------------------------------------------------------------------
// Gather neighbors + z_q_st + loss partials. 512 threads, 32-t tile.
// ---------------------------------------------------------------------------
#define GATHER_SMEM (512 * 33 * 4)

__global__ __launch_bounds__(512) void gather_kernel(const float* __restrict__ x,
                                                     const float* __restrict__ E,
                                                     float* __restrict__ out)
{
    extern __shared__ float s[];       // [512 d][33] padded
    __shared__ int   s_code[32][5];
    __shared__ float s_mask[32][5];
    __shared__ float red[512];
#define SG(d, t) s[(d) * 33 + (t)]

    int tid = threadIdx.x;
    int lane = tid & 31;
    int dgrp = tid >> 5;               // 0..15
    int n = blockIdx.y;
    int t0 = blockIdx.x * 32;
    const float* xp = x + (size_t)n * C_DIM * T_DIM + t0;

    for (int d = dgrp; d < 512; d += 16)
        SG(d, lane) = xp[(size_t)d * T_DIM + lane];

    if (tid < 32) {
        int m = n * T_DIM + t0 + tid;
        int kk = g_k[m];
        int k1 = kk >> 5, k2 = kk & 31;
        s_code[tid][0] = kk;                 s_mask[tid][0] = 1.f;
        s_code[tid][1] = (k1 + 1) * 32 + k2; s_mask[tid][1] = (k1 < 31) ? 1.f : 0.f;
        s_code[tid][2] = (k1 - 1) * 32 + k2; s_mask[tid][2] = (k1 > 0)  ? 1.f : 0.f;
        s_code[tid][3] = kk + 1;             s_mask[tid][3] = (k2 < 31) ? 1.f : 0.f;
        s_code[tid][4] = kk - 1;             s_mask[tid][4] = (k2 > 0)  ? 1.f : 0.f;
    }
    __syncthreads();

    float cacc = 0.f, sacc = 0.f;
    for (int t = 0; t < 32; t++) {
        int m = n * T_DIM + t0 + t;
        float* nbp = out + O_NB + (size_t)m * (5 * 512);
        int d = tid;                   // 512 threads cover all d
        float ze = SG(d, t);
        float zq = E[(size_t)s_code[t][0] * 512 + d];
        __stcs(&nbp[d], zq);
        float diff = zq - ze;
        cacc += diff * diff;
        sacc += diff * diff;
#pragma unroll
        for (int slot = 1; slot < 5; slot++) {
            float v = 0.f;
            if (s_mask[t][slot] != 0.f) v = E[(size_t)s_code[t][slot] * 512 + d];
            __stcs(&nbp[slot * 512 + d], v);
            float dd = ze - v;
            sacc += dd * dd;
        }
        SG(d, t) = zq;
    }
    __syncthreads();

    for (int d = dgrp; d < 512; d += 16)
        __stcs(&out[O_ZQST + (size_t)n * C_DIM * T_DIM + (size_t)d * T_DIM + t0 + lane],
               SG(d, lane));

    red[tid] = cacc;
    __syncthreads();
    for (int sft = 256; sft > 0; sft >>= 1) {
        if (tid < sft) red[tid] += red[tid + sft];
        __syncthreads();
    }
    float cblock = red[0];
    __syncthreads();
    red[tid] = sacc;
    __syncthreads();
    for (int sft = 256; sft > 0; sft >>= 1) {
        if (tid < sft) red[tid] += red[tid + sft];
        __syncthreads();
    }
    if (tid == 0) {
        int bid = blockIdx.y * gridDim.x + blockIdx.x;
        g_cpart[bid] = cblock;
        g_spart[bid] = red[0];
    }
#undef SG
}

__global__ void loss_kernel(float* __restrict__ out) {
    __shared__ double rc[256], rs[256];
    int tid = threadIdx.x;
    double c = 0.0, s = 0.0;
    for (int i = tid; i < NUM_GATHER_BLOCKS; i += 256) {
        c += (double)g_cpart[i];
        s += (double)g_spart[i];
    }
    rc[tid] = c; rs[tid] = s;
    __syncthreads();
    for (int sft = 128; sft > 0; sft >>= 1) {
        if (tid < sft) { rc[tid] += rc[tid + sft]; rs[tid] += rs[tid + sft]; }
        __syncthreads();
    }
    if (tid == 0) {
        double MD = (double)M_ROWS * (double)D_DIM;
        out[O_COMMIT] = (float)(2.0 * rc[0] / MD);
        out[O_SOM]    = (float)(rs[0] / (MD * 5.0));
    }
}

// ---------------------------------------------------------------------------
extern "C" void kernel_launch(void* const* d_in, const int* in_sizes, int n_in,
                              void* d_out, int out_size) {
    const float* x = (const float*)d_in[0];
    const float* E = (const float*)d_in[1];
    float* out = (float*)d_out;

    static int init = 0;
    if (!init) {
        cudaFuncSetAttribute(mma_dist_kernel,
                             cudaFuncAttributeMaxDynamicSharedMemorySize, DYN_SMEM);
        cudaFuncSetAttribute(gather_kernel,
                             cudaFuncAttributeMaxDynamicSharedMemorySize, GATHER_SMEM);
        init = 1;
    }

    dim3 gz(T_DIM / 32, C_DIM / 64, N_B);
    prep_z_kernel<<<gz, 256>>>(x);
    prep_e_kernel<<<(K_CODES * D_DIM) / 256, 256>>>(E);
    zsq_combine_kernel<<<M_ROWS / 256, 256>>>();
    esq_kernel<<<K_CODES, 128>>>(E);
    dim3 gd(K_CODES / BN, M_ROWS / BM);
    mma_dist_kernel<<<gd, 256, DYN_SMEM>>>(out);
    fixup_kernel<<<M_ROWS / 8, 256>>>(E, out);
    dim3 g(T_DIM / 32, N_B);
    gather_kernel<<<g, 512, GATHER_SMEM>>>(x, E, out);
    loss_kernel<<<1, 256>>>(out);
}

// round 8
// speedup vs baseline: 3.4850x; 1.0524x over previous
#include <cuda_runtime.h>
#include <cuda_bf16.h>
#include <cstdint>

// Problem constants
#define N_B    32
#define C_DIM  512
#define T_DIM  1024
#define D_DIM  512
#define K_CODES 1024
#define M_ROWS 32768

// Output layout (concatenation of reference return tuple, fp32)
#define O_ZQST   0UL
#define O_COMMIT 16777216UL
#define O_SOM    16777217UL
#define O_NB     16777218UL
#define O_DIST   100663298UL
#define O_K      134217730UL

#define NUM_GATHER_BLOCKS 1024    // 32 n * 32 t-tiles

// ---------------- scratch (device globals; no allocations) ----------------
static __device__ float g_zsq[M_ROWS];
static __device__ float g_zsqp[8][M_ROWS];
static __device__ float g_esq[K_CODES];
static __device__ int   g_k[M_ROWS];
static __device__ unsigned long long g_bmin[M_ROWS][8];   // per-(row, n-block) min key
static __device__ float g_cpart[NUM_GATHER_BLOCKS];
static __device__ float g_spart[NUM_GATHER_BLOCKS];

// bf16 operands + contiguous fp32 transposed z (for exact fixup / gather)
static __device__ __nv_bfloat16 g_z1[M_ROWS * D_DIM];
static __device__ __nv_bfloat16 g_e1[K_CODES * D_DIM];
static __device__ float g_zt[M_ROWS * D_DIM];

// ---------------- PTX helpers (baseline sm_80+ PTX, valid on compute_103) ----
__device__ __forceinline__ void cp16(uint32_t dst, const void* src) {
    asm volatile("cp.async.cg.shared.global [%0], [%1], 16;" :: "r"(dst), "l"(src));
}
#define CP_COMMIT() asm volatile("cp.async.commit_group;" ::: "memory")
#define CP_WAIT2()  asm volatile("cp.async.wait_group 2;" ::: "memory")

#define LDSM4(r0, r1, r2, r3, addr)                                        \
    asm volatile("ldmatrix.sync.aligned.m8n8.x4.shared.b16 {%0,%1,%2,%3}, [%4];" \
                 : "=r"(r0), "=r"(r1), "=r"(r2), "=r"(r3) : "r"(addr))

__device__ __forceinline__ void mma16816(float* c, const uint32_t* a, const uint32_t* b) {
    asm volatile(
        "mma.sync.aligned.m16n8k16.row.col.f32.bf16.bf16.f32 "
        "{%0,%1,%2,%3}, {%4,%5,%6,%7}, {%8,%9}, {%0,%1,%2,%3};"
        : "+f"(c[0]), "+f"(c[1]), "+f"(c[2]), "+f"(c[3])
        : "r"(a[0]), "r"(a[1]), "r"(a[2]), "r"(a[3]), "r"(b[0]), "r"(b[1]));
}

// ---------------------------------------------------------------------------
// Prep: transpose x -> z rows (m-major), bf16 + fp32 copies + zsq partials
// ---------------------------------------------------------------------------
__global__ void prep_z_kernel(const float* __restrict__ x) {
    __shared__ float s[64][33];
    int tid = threadIdx.x;
    int t0 = blockIdx.x * 32, d0 = blockIdx.y * 64, n = blockIdx.z;
    const float* xp = x + (size_t)n * C_DIM * T_DIM + (size_t)d0 * T_DIM + t0;
#pragma unroll
    for (int w = 0; w < 8; w++) {
        int idx = tid + w * 256;
        s[idx >> 5][idx & 31] = xp[(size_t)(idx >> 5) * T_DIM + (idx & 31)];
    }
    __syncthreads();
#pragma unroll
    for (int w = 0; w < 4; w++) {
        int idx = tid + w * 256;
        int dp = idx & 31, tt = idx >> 5;
        int m = n * T_DIM + t0 + tt;
        size_t o = (size_t)m * 256 + (d0 >> 1) + dp;
        float v0 = s[2 * dp][tt];
        float v1 = s[2 * dp + 1][tt];
        __nv_bfloat162 p1;
        p1.x = __float2bfloat16_rn(v0);
        p1.y = __float2bfloat16_rn(v1);
        ((__nv_bfloat162*)g_z1)[o] = p1;
        float2 zf; zf.x = v0; zf.y = v1;
        *(float2*)(g_zt + (size_t)m * 512 + d0 + 2 * dp) = zf;
    }
    if (tid < 32) {
        float acc = 0.f;
#pragma unroll
        for (int d = 0; d < 64; d++) {
            float v = s[d][tid];
            acc += v * v;
        }
        g_zsqp[d0 >> 6][n * T_DIM + t0 + tid] = acc;
    }
}

__global__ void zsq_combine_kernel() {
    int m = blockIdx.x * 256 + threadIdx.x;
    float acc = 0.f;
#pragma unroll
    for (int q = 0; q < 8; q++) acc += g_zsqp[q][m];
    g_zsq[m] = acc;
}

// esq + bf16 conversion of E in one pass
__global__ void esq_kernel(const float* __restrict__ E) {
    __shared__ float red[128];
    int code = blockIdx.x;
    const float* e = E + (size_t)code * D_DIM;
    float acc = 0.f;
    for (int d = threadIdx.x; d < D_DIM; d += 128) {
        float v = e[d];
        g_e1[(size_t)code * D_DIM + d] = __float2bfloat16_rn(v);
        acc += v * v;
    }
    red[threadIdx.x] = acc;
    __syncthreads();
    for (int s = 64; s > 0; s >>= 1) {
        if (threadIdx.x < s) red[threadIdx.x] += red[threadIdx.x + s];
        __syncthreads();
    }
    if (threadIdx.x == 0) g_esq[code] = red[0];
}

// ---------------------------------------------------------------------------
// Distance GEMM via mma.sync (HMMA bf16) + per-block argmin keys.
// ---------------------------------------------------------------------------
#define BM 128
#define BN 128
#define BK 32
#define ASTRIDE 80
#define STAGE_BYTES (2 * BM * ASTRIDE)
#define NSTAGES 4
#define DYN_SMEM (NSTAGES * STAGE_BYTES)
#define KITERS 16

__device__ __forceinline__ void load_stage(
    uint32_t sbase, int tid, int m0, int n0, int it)
{
    int k0 = it * BK;
#pragma unroll
    for (int q = 0; q < 2; q++) {
        int ch = tid + q * 256;
        int row = ch >> 2, c = ch & 3;
        cp16(sbase + row * ASTRIDE + c * 16,
             g_z1 + (size_t)(m0 + row) * 512 + k0 + c * 8);
    }
#pragma unroll
    for (int q = 0; q < 2; q++) {
        int ch = tid + q * 256;
        int row = ch >> 2, c = ch & 3;
        cp16(sbase + BM * ASTRIDE + row * ASTRIDE + c * 16,
             g_e1 + (size_t)(n0 + row) * 512 + k0 + c * 8);
    }
    CP_COMMIT();
}

__global__ __launch_bounds__(256, 2) void mma_dist_kernel(float* __restrict__ out) {
    extern __shared__ char sm[];
    uint32_t smb;
    asm("{ .reg .u64 t; cvta.to.shared.u64 t, %1; cvt.u32.u64 %0, t; }"
        : "=r"(smb) : "l"(sm));

    int tid = threadIdx.x, lane = tid & 31, wid = tid >> 5;
    int wm = wid >> 2, wn = wid & 3;
    int n0 = blockIdx.x * BN, m0 = blockIdx.y * BM;

    int t8 = lane >> 3, lr = lane & 7;
    uint32_t offA[4][2], offB[2][2];
#pragma unroll
    for (int mt = 0; mt < 4; mt++)
#pragma unroll
        for (int ks = 0; ks < 2; ks++) {
            int row = wm * 64 + mt * 16 + (t8 & 1) * 8 + lr;
            int col = ks * 16 + (t8 >> 1) * 8;
            offA[mt][ks] = row * ASTRIDE + col * 2;
        }
#pragma unroll
    for (int np = 0; np < 2; np++)
#pragma unroll
        for (int ks = 0; ks < 2; ks++) {
            int row = wn * 32 + np * 16 + (t8 >> 1) * 8 + lr;
            int col = ks * 16 + (t8 & 1) * 8;
            offB[np][ks] = BM * ASTRIDE + row * ASTRIDE + col * 2;
        }

    float acc[4][4][4];
#pragma unroll
    for (int i = 0; i < 4; i++)
#pragma unroll
        for (int j = 0; j < 4; j++)
#pragma unroll
            for (int q = 0; q < 4; q++) acc[i][j][q] = 0.f;

#pragma unroll
    for (int s = 0; s < NSTAGES - 1; s++)
        load_stage(smb + s * STAGE_BYTES, tid, m0, n0, s);

    for (int it = 0; it < KITERS; it++) {
        CP_WAIT2();
        __syncthreads();
        uint32_t sbase = smb + (it & 3) * STAGE_BYTES;
#pragma unroll
        for (int ks = 0; ks < 2; ks++) {
            uint32_t a[4][4], b[4][2];
#pragma unroll
            for (int mt = 0; mt < 4; mt++)
                LDSM4(a[mt][0], a[mt][1], a[mt][2], a[mt][3], sbase + offA[mt][ks]);
#pragma unroll
            for (int np = 0; np < 2; np++)
                LDSM4(b[2 * np][0], b[2 * np][1], b[2 * np + 1][0], b[2 * np + 1][1],
                      sbase + offB[np][ks]);
#pragma unroll
            for (int mt = 0; mt < 4; mt++)
#pragma unroll
                for (int nt = 0; nt < 4; nt++)
                    mma16816(acc[mt][nt], a[mt], b[nt]);
        }
        int nx = it + NSTAGES - 1;
        if (nx < KITERS)
            load_stage(smb + (nx & 3) * STAGE_BYTES, tid, m0, n0, nx);
        else
            CP_COMMIT();
    }

    // ---------------- epilogue ----------------
    __syncthreads();
    unsigned long long* keyrow = (unsigned long long*)sm;   // [128][4]

#pragma unroll
    for (int mt = 0; mt < 4; mt++) {
#pragma unroll
        for (int half = 0; half < 2; half++) {
            int rl = wm * 64 + mt * 16 + half * 8 + (lane >> 2);
            int row = m0 + rl;
            float zr = g_zsq[row];
            float best = 3.4e38f;
            int bi = 0;
#pragma unroll
            for (int nt = 0; nt < 4; nt++) {
                int col = n0 + wn * 32 + nt * 8 + (lane & 3) * 2;
                float d0 = fmaf(-2.f, acc[mt][nt][half * 2 + 0], zr) + g_esq[col];
                float d1 = fmaf(-2.f, acc[mt][nt][half * 2 + 1], zr) + g_esq[col + 1];
                float2 st; st.x = d0; st.y = d1;
                __stcs((float2*)(out + O_DIST + (size_t)row * K_CODES + col), st);
                if (d0 < best) { best = d0; bi = col; }
                if (d1 < best) { best = d1; bi = col + 1; }
            }
            unsigned long long key =
                ((unsigned long long)__float_as_uint(best) << 32) | (unsigned)bi;
#pragma unroll
            for (int ofs = 1; ofs <= 2; ofs <<= 1) {
                unsigned long long o = __shfl_xor_sync(0xffffffffu, key, ofs);
                if (o < key) key = o;
            }
            if ((lane & 3) == 0) keyrow[rl * 4 + wn] = key;
        }
    }
    __syncthreads();
    if (tid < 128) {
        unsigned long long k0 = keyrow[tid * 4 + 0];
        unsigned long long k1 = keyrow[tid * 4 + 1];
        unsigned long long k2 = keyrow[tid * 4 + 2];
        unsigned long long k3 = keyrow[tid * 4 + 3];
        if (k1 < k0) k0 = k1;
        if (k2 < k0) k0 = k2;
        if (k3 < k0) k0 = k3;
        g_bmin[m0 + tid][blockIdx.x] = k0;     // deterministic, no atomics
    }
}

// ---------------------------------------------------------------------------
// Fixup: per-row, read 8 block-min keys; scan only blocks whose min is within
// EPS of the global min (typically 1 block = 512B instead of 4KB). Then lazy
// re-evaluation: single candidate -> done; else fp64 dot + reference-mimicking
// fp32 assembly d = fl32( fl32(zsq - 2*dotf) + esq ); ties -> lower index.
// ---------------------------------------------------------------------------
#define FIX_EPS 0.1f
#define MAXCAND 64

__global__ __launch_bounds__(256) void fixup_kernel(const float* __restrict__ E,
                                                    float* __restrict__ out) {
    __shared__ int s_cnt[8];
    __shared__ int s_cand[8][MAXCAND];
    int w = threadIdx.x >> 5, lane = threadIdx.x & 31;
    int m = blockIdx.x * 8 + w;
    if (lane == 0) s_cnt[w] = 0;
    __syncwarp();

    unsigned long long mykey = (lane < 8) ? g_bmin[m][lane] : 0xFFFFFFFFFFFFFFFFull;
    unsigned long long gmin = mykey;
#pragma unroll
    for (int ofs = 16; ofs > 0; ofs >>= 1) {
        unsigned long long o = __shfl_xor_sync(0xffffffffu, gmin, ofs);
        if (o < gmin) gmin = o;
    }
    float thr = __uint_as_float((unsigned)(gmin >> 32)) + FIX_EPS;
    const float* drow = out + O_DIST + (size_t)m * K_CODES;

#pragma unroll
    for (int b = 0; b < 8; b++) {
        unsigned long long kb = __shfl_sync(0xffffffffu, mykey, b);
        if (__uint_as_float((unsigned)(kb >> 32)) <= thr) {
            int c = b * 128 + lane;
#pragma unroll
            for (int q = 0; q < 4; q++, c += 32) {
                if (__ldcs(&drow[c]) <= thr) {
                    int p = atomicAdd(&s_cnt[w], 1);
                    if (p < MAXCAND) s_cand[w][p] = c;
                }
            }
        }
    }
    __syncwarp();
    int ncand = min(s_cnt[w], MAXCAND);

    int bi;
    if (ncand == 1) {
        bi = s_cand[w][0];
    } else {
        const float* zrow = g_zt + (size_t)m * 512;
        double zc[16];
#pragma unroll
        for (int q = 0; q < 16; q++) zc[q] = (double)zrow[lane + q * 32];
        float zsq_m = g_zsq[m];
        float bd = 3.4e38f;
        bi = 0x7FFFFFFF;
        for (int j = 0; j < ncand; j++) {
            int c = s_cand[w][j];
            const float* e = E + (size_t)c * 512;
            double s = 0.0;
#pragma unroll
            for (int q = 0; q < 16; q++)
                s += zc[q] * (double)e[lane + q * 32];
#pragma unroll
            for (int ofs = 16; ofs > 0; ofs >>= 1)
                s += __shfl_xor_sync(0xffffffffu, s, ofs);
            float dotf = (float)s;
            float t1 = zsq_m - 2.0f * dotf;
            float d = t1 + g_esq[c];
            if (d < bd || (d == bd && c < bi)) { bd = d; bi = c; }
        }
    }
    if (lane == 0) {
        g_k[m] = bi;
        out[O_K + m] = (float)bi;
    }
}

// ---------------------------------------------------------------------------
// Gather neighbors + z_q_st + loss partials. 512 threads, 32-t tile.
// float2 loads/stores (O_NB is only 8B-aligned). ze comes straight from g_zt
// (contiguous); zq staged in smem [t][514] for the transposed z_q_st write.
// ---------------------------------------------------------------------------
#define SG_STRIDE 514
#define GATHER_SMEM (32 * SG_STRIDE * 4)   // 65792 bytes

__global__ __launch_bounds__(512) void gather_kernel(const float* __restrict__ E,
                                                     float* __restrict__ out)
{
    extern __shared__ float s[];           // [32 t][SG_STRIDE]
    __shared__ int   s_code[32][5];
    __shared__ float s_mask[32][5];
    __shared__ float red[512];

    int tid = threadIdx.x;
    int dq = tid & 255;                    // d-pair index: d = dq*2, dq*2+1
    int tg = tid >> 8;                     // 0..1 (16 t each)
    int n = blockIdx.y;
    int t0 = blockIdx.x * 32;

    if (tid < 32) {
        int m = n * T_DIM + t0 + tid;
        int kk = g_k[m];
        int k1 = kk >> 5, k2 = kk & 31;
        s_code[tid][0] = kk;                 s_mask[tid][0] = 1.f;
        s_code[tid][1] = (k1 + 1) * 32 + k2; s_mask[tid][1] = (k1 < 31) ? 1.f : 0.f;
        s_code[tid][2] = (k1 - 1) * 32 + k2; s_mask[tid][2] = (k1 > 0)  ? 1.f : 0.f;
        s_code[tid][3] = kk + 1;             s_mask[tid][3] = (k2 < 31) ? 1.f : 0.f;
        s_code[tid][4] = kk - 1;             s_mask[tid][4] = (k2 > 0)  ? 1.f : 0.f;
    }
    __syncthreads();

    float cacc = 0.f, sacc = 0.f;
    for (int i = 0; i < 16; i++) {
        int t = tg * 16 + i;
        int m = n * T_DIM + t0 + t;
        float2 ze = *(const float2*)(g_zt + (size_t)m * 512 + dq * 2);
        float* nbp = out + O_NB + (size_t)m * (5 * 512);
        float2 zq = *(const float2*)(E + (size_t)s_code[t][0] * 512 + dq * 2);
        __stcs((float2*)(nbp + dq * 2), zq);
        float dx = zq.x - ze.x, dy = zq.y - ze.y;
        cacc += dx * dx + dy * dy;
        sacc += dx * dx + dy * dy;
        *(float2*)&s[t * SG_STRIDE + dq * 2] = zq;
#pragma unroll
        for (int slot = 1; slot < 5; slot++) {
            float2 v;
            if (s_mask[t][slot] != 0.f)
                v = *(const float2*)(E + (size_t)s_code[t][slot] * 512 + dq * 2);
            else { v.x = 0.f; v.y = 0.f; }
            __stcs((float2*)(nbp + slot * 512 + dq * 2), v);
            float ax = ze.x - v.x, ay = ze.y - v.y;
            sacc += ax * ax + ay * ay;
        }
    }
    __syncthreads();

    // z_q_st[n, d, t0+lane] from staged [t][d]
    {
        int lane = tid & 31;
        int dgrp = tid >> 5;               // 0..15
        for (int d = dgrp; d < 512; d += 16)
            __stcs(&out[O_ZQST + (size_t)n * C_DIM * T_DIM + (size_t)d * T_DIM + t0 + lane],
                   s[lane * SG_STRIDE + d]);
    }

    red[tid] = cacc;
    __syncthreads();
    for (int sft = 256; sft > 0; sft >>= 1) {
        if (tid < sft) red[tid] += red[tid + sft];
        __syncthreads();
    }
    float cblock = red[0];
    __syncthreads();
    red[tid] = sacc;
    __syncthreads();
    for (int sft = 256; sft > 0; sft >>= 1) {
        if (tid < sft) red[tid] += red[tid + sft];
        __syncthreads();
    }
    if (tid == 0) {
        int bid = blockIdx.y * gridDim.x + blockIdx.x;
        g_cpart[bid] = cblock;
        g_spart[bid] = red[0];
    }
}

__global__ void loss_kernel(float* __restrict__ out) {
    __shared__ double rc[256], rs[256];
    int tid = threadIdx.x;
    double c = 0.0, s = 0.0;
    for (int i = tid; i < NUM_GATHER_BLOCKS; i += 256) {
        c += (double)g_cpart[i];
        s += (double)g_spart[i];
    }
    rc[tid] = c; rs[tid] = s;
    __syncthreads();
    for (int sft = 128; sft > 0; sft >>= 1) {
        if (tid < sft) { rc[tid] += rc[tid + sft]; rs[tid] += rs[tid + sft]; }
        __syncthreads();
    }
    if (tid == 0) {
        double MD = (double)M_ROWS * (double)D_DIM;
        out[O_COMMIT] = (float)(2.0 * rc[0] / MD);
        out[O_SOM]    = (float)(rs[0] / (MD * 5.0));
    }
}

// ---------------------------------------------------------------------------
extern "C" void kernel_launch(void* const* d_in, const int* in_sizes, int n_in,
                              void* d_out, int out_size) {
    const float* x = (const float*)d_in[0];
    const float* E = (const float*)d_in[1];
    float* out = (float*)d_out;

    static int init = 0;
    if (!init) {
        cudaFuncSetAttribute(mma_dist_kernel,
                             cudaFuncAttributeMaxDynamicSharedMemorySize, DYN_SMEM);
        cudaFuncSetAttribute(gather_kernel,
                             cudaFuncAttributeMaxDynamicSharedMemorySize, GATHER_SMEM);
        init = 1;
    }

    dim3 gz(T_DIM / 32, C_DIM / 64, N_B);
    prep_z_kernel<<<gz, 256>>>(x);
    esq_kernel<<<K_CODES, 128>>>(E);
    zsq_combine_kernel<<<M_ROWS / 256, 256>>>();
    dim3 gd(K_CODES / BN, M_ROWS / BM);
    mma_dist_kernel<<<gd, 256, DYN_SMEM>>>(out);
    fixup_kernel<<<M_ROWS / 8, 256>>>(E, out);
    dim3 g(T_DIM / 32, N_B);
    gather_kernel<<<g, 512, GATHER_SMEM>>>(E, out);
    loss_kernel<<<1, 256>>>(out);
}

// round 9
// speedup vs baseline: 3.5180x; 1.0095x over previous
#include <cuda_runtime.h>
#include <cuda_bf16.h>
#include <cstdint>

// Problem constants
#define N_B    32
#define C_DIM  512
#define T_DIM  1024
#define D_DIM  512
#define K_CODES 1024
#define M_ROWS 32768

// Output layout (concatenation of reference return tuple, fp32)
#define O_ZQST   0UL
#define O_COMMIT 16777216UL
#define O_SOM    16777217UL
#define O_NB     16777218UL
#define O_DIST   100663298UL
#define O_K      134217730UL

#define NUM_GATHER_BLOCKS 1024    // 32 n * 32 t-tiles

// ---------------- scratch (device globals; no allocations) ----------------
static __device__ float g_zsq[M_ROWS];
static __device__ float g_zsqp[8][M_ROWS];
static __device__ float g_esq[K_CODES];
static __device__ int   g_k[M_ROWS];
static __device__ unsigned long long g_bmin[M_ROWS][8];   // per-(row, n-block) min key
static __device__ float g_cpart[NUM_GATHER_BLOCKS];
static __device__ float g_spart[NUM_GATHER_BLOCKS];

// bf16 operands + contiguous fp32 transposed z (for exact fixup / gather)
static __device__ __nv_bfloat16 g_z1[M_ROWS * D_DIM];
static __device__ __nv_bfloat16 g_e1[K_CODES * D_DIM];
static __device__ float g_zt[M_ROWS * D_DIM];

// ---------------- PTX helpers (baseline sm_80+ PTX, valid on compute_103) ----
__device__ __forceinline__ void cp16(uint32_t dst, const void* src) {
    asm volatile("cp.async.cg.shared.global [%0], [%1], 16;" :: "r"(dst), "l"(src));
}
#define CP_COMMIT() asm volatile("cp.async.commit_group;" ::: "memory")
#define CP_WAIT2()  asm volatile("cp.async.wait_group 2;" ::: "memory")

#define LDSM4(r0, r1, r2, r3, addr)                                        \
    asm volatile("ldmatrix.sync.aligned.m8n8.x4.shared.b16 {%0,%1,%2,%3}, [%4];" \
                 : "=r"(r0), "=r"(r1), "=r"(r2), "=r"(r3) : "r"(addr))

__device__ __forceinline__ void mma16816(float* c, const uint32_t* a, const uint32_t* b) {
    asm volatile(
        "mma.sync.aligned.m16n8k16.row.col.f32.bf16.bf16.f32 "
        "{%0,%1,%2,%3}, {%4,%5,%6,%7}, {%8,%9}, {%0,%1,%2,%3};"
        : "+f"(c[0]), "+f"(c[1]), "+f"(c[2]), "+f"(c[3])
        : "r"(a[0]), "r"(a[1]), "r"(a[2]), "r"(a[3]), "r"(b[0]), "r"(b[1]));
}

// ---------------------------------------------------------------------------
// Prep: transpose x -> z rows (m-major), bf16 + fp32 copies + zsq partials
// ---------------------------------------------------------------------------
__global__ void prep_z_kernel(const float* __restrict__ x) {
    __shared__ float s[64][33];
    int tid = threadIdx.x;
    int t0 = blockIdx.x * 32, d0 = blockIdx.y * 64, n = blockIdx.z;
    const float* xp = x + (size_t)n * C_DIM * T_DIM + (size_t)d0 * T_DIM + t0;
#pragma unroll
    for (int w = 0; w < 8; w++) {
        int idx = tid + w * 256;
        s[idx >> 5][idx & 31] = xp[(size_t)(idx >> 5) * T_DIM + (idx & 31)];
    }
    __syncthreads();
#pragma unroll
    for (int w = 0; w < 4; w++) {
        int idx = tid + w * 256;
        int dp = idx & 31, tt = idx >> 5;
        int m = n * T_DIM + t0 + tt;
        size_t o = (size_t)m * 256 + (d0 >> 1) + dp;
        float v0 = s[2 * dp][tt];
        float v1 = s[2 * dp + 1][tt];
        __nv_bfloat162 p1;
        p1.x = __float2bfloat16_rn(v0);
        p1.y = __float2bfloat16_rn(v1);
        ((__nv_bfloat162*)g_z1)[o] = p1;
        float2 zf; zf.x = v0; zf.y = v1;
        *(float2*)(g_zt + (size_t)m * 512 + d0 + 2 * dp) = zf;
    }
    if (tid < 32) {
        float acc = 0.f;
#pragma unroll
        for (int d = 0; d < 64; d++) {
            float v = s[d][tid];
            acc += v * v;
        }
        g_zsqp[d0 >> 6][n * T_DIM + t0 + tid] = acc;
    }
}

__global__ void zsq_combine_kernel() {
    int m = blockIdx.x * 256 + threadIdx.x;
    float acc = 0.f;
#pragma unroll
    for (int q = 0; q < 8; q++) acc += g_zsqp[q][m];
    g_zsq[m] = acc;
}

// esq + bf16 conversion of E in one pass
__global__ void esq_kernel(const float* __restrict__ E) {
    __shared__ float red[128];
    int code = blockIdx.x;
    const float* e = E + (size_t)code * D_DIM;
    float acc = 0.f;
    for (int d = threadIdx.x; d < D_DIM; d += 128) {
        float v = e[d];
        g_e1[(size_t)code * D_DIM + d] = __float2bfloat16_rn(v);
        acc += v * v;
    }
    red[threadIdx.x] = acc;
    __syncthreads();
    for (int s = 64; s > 0; s >>= 1) {
        if (threadIdx.x < s) red[threadIdx.x] += red[threadIdx.x + s];
        __syncthreads();
    }
    if (threadIdx.x == 0) g_esq[code] = red[0];
}

// ---------------------------------------------------------------------------
// Distance GEMM via mma.sync (HMMA bf16) + per-block argmin keys.
// 128 threads, 4 warps (2x2), warp tile 64x64 (smem-crossbar-optimal:
// 125 B LDSM traffic per MMA vs 187 with 64x32). Prefetch-first multistage.
// ---------------------------------------------------------------------------
#define BM 128
#define BN 128
#define BK 32
#define ASTRIDE 80
#define STAGE_BYTES (2 * BM * ASTRIDE)
#define NSTAGES 4
#define DYN_SMEM (NSTAGES * STAGE_BYTES)
#define KITERS 16

__device__ __forceinline__ void load_stage(
    uint32_t sbase, int tid, int m0, int n0, int it)
{
    int k0 = it * BK;
#pragma unroll
    for (int q = 0; q < 4; q++) {
        int ch = tid + q * 128;
        int row = ch >> 2, c = ch & 3;
        cp16(sbase + row * ASTRIDE + c * 16,
             g_z1 + (size_t)(m0 + row) * 512 + k0 + c * 8);
    }
#pragma unroll
    for (int q = 0; q < 4; q++) {
        int ch = tid + q * 128;
        int row = ch >> 2, c = ch & 3;
        cp16(sbase + BM * ASTRIDE + row * ASTRIDE + c * 16,
             g_e1 + (size_t)(n0 + row) * 512 + k0 + c * 8);
    }
    CP_COMMIT();
}

__global__ __launch_bounds__(128, 2) void mma_dist_kernel(float* __restrict__ out) {
    extern __shared__ char sm[];
    uint32_t smb;
    asm("{ .reg .u64 t; cvta.to.shared.u64 t, %1; cvt.u32.u64 %0, t; }"
        : "=r"(smb) : "l"(sm));

    int tid = threadIdx.x, lane = tid & 31, wid = tid >> 5;
    int wm = wid >> 1, wn = wid & 1;           // 2x2 warp grid, 64x64 tiles
    int n0 = blockIdx.x * BN, m0 = blockIdx.y * BM;

    int t8 = lane >> 3, lr = lane & 7;
    uint32_t offA[4][2], offB[4][2];
#pragma unroll
    for (int mt = 0; mt < 4; mt++)
#pragma unroll
        for (int ks = 0; ks < 2; ks++) {
            int row = wm * 64 + mt * 16 + (t8 & 1) * 8 + lr;
            int col = ks * 16 + (t8 >> 1) * 8;
            offA[mt][ks] = row * ASTRIDE + col * 2;
        }
#pragma unroll
    for (int np = 0; np < 4; np++)
#pragma unroll
        for (int ks = 0; ks < 2; ks++) {
            int row = wn * 64 + np * 16 + (t8 >> 1) * 8 + lr;
            int col = ks * 16 + (t8 & 1) * 8;
            offB[np][ks] = BM * ASTRIDE + row * ASTRIDE + col * 2;
        }

    float acc[4][8][4];
#pragma unroll
    for (int i = 0; i < 4; i++)
#pragma unroll
        for (int j = 0; j < 8; j++)
#pragma unroll
            for (int q = 0; q < 4; q++) acc[i][j][q] = 0.f;

#pragma unroll
    for (int s = 0; s < NSTAGES - 1; s++)
        load_stage(smb + s * STAGE_BYTES, tid, m0, n0, s);

    for (int it = 0; it < KITERS; it++) {
        CP_WAIT2();
        __syncthreads();
        // prefetch-first: next stage's loads overlap this iter's compute
        int nx = it + NSTAGES - 1;
        if (nx < KITERS)
            load_stage(smb + (nx & 3) * STAGE_BYTES, tid, m0, n0, nx);
        else
            CP_COMMIT();
        uint32_t sbase = smb + (it & 3) * STAGE_BYTES;
#pragma unroll
        for (int ks = 0; ks < 2; ks++) {
            uint32_t a[4][4], b[8][2];
#pragma unroll
            for (int mt = 0; mt < 4; mt++)
                LDSM4(a[mt][0], a[mt][1], a[mt][2], a[mt][3], sbase + offA[mt][ks]);
#pragma unroll
            for (int np = 0; np < 4; np++)
                LDSM4(b[2 * np][0], b[2 * np][1], b[2 * np + 1][0], b[2 * np + 1][1],
                      sbase + offB[np][ks]);
#pragma unroll
            for (int mt = 0; mt < 4; mt++)
#pragma unroll
                for (int nt = 0; nt < 8; nt++)
                    mma16816(acc[mt][nt], a[mt], b[nt]);
        }
    }

    // ---------------- epilogue ----------------
    __syncthreads();
    unsigned long long* keyrow = (unsigned long long*)sm;   // [128][2]

#pragma unroll
    for (int mt = 0; mt < 4; mt++) {
#pragma unroll
        for (int half = 0; half < 2; half++) {
            int rl = wm * 64 + mt * 16 + half * 8 + (lane >> 2);
            int row = m0 + rl;
            float zr = g_zsq[row];
            float best = 3.4e38f;
            int bi = 0;
#pragma unroll
            for (int nt = 0; nt < 8; nt++) {
                int col = n0 + wn * 64 + nt * 8 + (lane & 3) * 2;
                float d0 = fmaf(-2.f, acc[mt][nt][half * 2 + 0], zr) + g_esq[col];
                float d1 = fmaf(-2.f, acc[mt][nt][half * 2 + 1], zr) + g_esq[col + 1];
                float2 st; st.x = d0; st.y = d1;
                __stcs((float2*)(out + O_DIST + (size_t)row * K_CODES + col), st);
                if (d0 < best) { best = d0; bi = col; }
                if (d1 < best) { best = d1; bi = col + 1; }
            }
            unsigned long long key =
                ((unsigned long long)__float_as_uint(best) << 32) | (unsigned)bi;
#pragma unroll
            for (int ofs = 1; ofs <= 2; ofs <<= 1) {
                unsigned long long o = __shfl_xor_sync(0xffffffffu, key, ofs);
                if (o < key) key = o;
            }
            if ((lane & 3) == 0) keyrow[rl * 2 + wn] = key;
        }
    }
    __syncthreads();
    {
        unsigned long long k0 = keyrow[tid * 2 + 0];
        unsigned long long k1 = keyrow[tid * 2 + 1];
        if (k1 < k0) k0 = k1;
        g_bmin[m0 + tid][blockIdx.x] = k0;     // deterministic, no atomics
    }
}

// ---------------------------------------------------------------------------
// Fixup: per-row, read 8 block-min keys; scan only blocks whose min is within
// EPS of the global min. Lazy re-evaluation: single candidate -> done; else
// fp64 dot + reference-mimicking fp32 assembly; ties -> lower index.
// ---------------------------------------------------------------------------
#define FIX_EPS 0.1f
#define MAXCAND 64

__global__ __launch_bounds__(256) void fixup_kernel(const float* __restrict__ E,
                                                    float* __restrict__ out) {
    __shared__ int s_cnt[8];
    __shared__ int s_cand[8][MAXCAND];
    int w = threadIdx.x >> 5, lane = threadIdx.x & 31;
    int m = blockIdx.x * 8 + w;
    if (lane == 0) s_cnt[w] = 0;
    __syncwarp();

    unsigned long long mykey = (lane < 8) ? g_bmin[m][lane] : 0xFFFFFFFFFFFFFFFFull;
    unsigned long long gmin = mykey;
#pragma unroll
    for (int ofs = 16; ofs > 0; ofs >>= 1) {
        unsigned long long o = __shfl_xor_sync(0xffffffffu, gmin, ofs);
        if (o < gmin) gmin = o;
    }
    float thr = __uint_as_float((unsigned)(gmin >> 32)) + FIX_EPS;
    const float* drow = out + O_DIST + (size_t)m * K_CODES;

#pragma unroll
    for (int b = 0; b < 8; b++) {
        unsigned long long kb = __shfl_sync(0xffffffffu, mykey, b);
        if (__uint_as_float((unsigned)(kb >> 32)) <= thr) {
            int c = b * 128 + lane;
#pragma unroll
            for (int q = 0; q < 4; q++, c += 32) {
                if (__ldcs(&drow[c]) <= thr) {
                    int p = atomicAdd(&s_cnt[w], 1);
                    if (p < MAXCAND) s_cand[w][p] = c;
                }
            }
        }
    }
    __syncwarp();
    int ncand = min(s_cnt[w], MAXCAND);

    int bi;
    if (ncand == 1) {
        bi = s_cand[w][0];
    } else {
        const float* zrow = g_zt + (size_t)m * 512;
        double zc[16];
#pragma unroll
        for (int q = 0; q < 16; q++) zc[q] = (double)zrow[lane + q * 32];
        float zsq_m = g_zsq[m];
        float bd = 3.4e38f;
        bi = 0x7FFFFFFF;
        for (int j = 0; j < ncand; j++) {
            int c = s_cand[w][j];
            const float* e = E + (size_t)c * 512;
            double s = 0.0;
#pragma unroll
            for (int q = 0; q < 16; q++)
                s += zc[q] * (double)e[lane + q * 32];
#pragma unroll
            for (int ofs = 16; ofs > 0; ofs >>= 1)
                s += __shfl_xor_sync(0xffffffffu, s, ofs);
            float dotf = (float)s;
            float t1 = zsq_m - 2.0f * dotf;
            float d = t1 + g_esq[c];
            if (d < bd || (d == bd && c < bi)) { bd = d; bi = c; }
        }
    }
    if (lane == 0) {
        g_k[m] = bi;
        out[O_K + m] = (float)bi;
    }
}

// ---------------------------------------------------------------------------
// Gather neighbors + z_q_st + loss partials. 512 threads, 32-t tile.
// ---------------------------------------------------------------------------
#define SG_STRIDE 514
#define GATHER_SMEM (32 * SG_STRIDE * 4)   // 65792 bytes

__global__ __launch_bounds__(512) void gather_kernel(const float* __restrict__ E,
                                                     float* __restrict__ out)
{
    extern __shared__ float s[];           // [32 t][SG_STRIDE]
    __shared__ int   s_code[32][5];
    __shared__ float s_mask[32][5];
    __shared__ float red[512];

    int tid = threadIdx.x;
    int dq = tid & 255;
    int tg = tid >> 8;
    int n = blockIdx.y;
    int t0 = blockIdx.x * 32;

    if (tid < 32) {
        int m = n * T_DIM + t0 + tid;
        int kk = g_k[m];
        int k1 = kk >> 5, k2 = kk & 31;
        s_code[tid][0] = kk;                 s_mask[tid][0] = 1.f;
        s_code[tid][1] = (k1 + 1) * 32 + k2; s_mask[tid][1] = (k1 < 31) ? 1.f : 0.f;
        s_code[tid][2] = (k1 - 1) * 32 + k2; s_mask[tid][2] = (k1 > 0)  ? 1.f : 0.f;
        s_code[tid][3] = kk + 1;             s_mask[tid][3] = (k2 < 31) ? 1.f : 0.f;
        s_code[tid][4] = kk - 1;             s_mask[tid][4] = (k2 > 0)  ? 1.f : 0.f;
    }
    __syncthreads();

    float cacc = 0.f, sacc = 0.f;
    for (int i = 0; i < 16; i++) {
        int t = tg * 16 + i;
        int m = n * T_DIM + t0 + t;
        float2 ze = *(const float2*)(g_zt + (size_t)m * 512 + dq * 2);
        float* nbp = out + O_NB + (size_t)m * (5 * 512);
        float2 zq = *(const float2*)(E + (size_t)s_code[t][0] * 512 + dq * 2);
        __stcs((float2*)(nbp + dq * 2), zq);
        float dx = zq.x - ze.x, dy = zq.y - ze.y;
        cacc += dx * dx + dy * dy;
        sacc += dx * dx + dy * dy;
        *(float2*)&s[t * SG_STRIDE + dq * 2] = zq;
#pragma unroll
        for (int slot = 1; slot < 5; slot++) {
            float2 v;
            if (s_mask[t][slot] != 0.f)
                v = *(const float2*)(E + (size_t)s_code[t][slot] * 512 + dq * 2);
            else { v.x = 0.f; v.y = 0.f; }
            __stcs((float2*)(nbp + slot * 512 + dq * 2), v);
            float ax = ze.x - v.x, ay = ze.y - v.y;
            sacc += ax * ax + ay * ay;
        }
    }
    __syncthreads();

    {
        int lane = tid & 31;
        int dgrp = tid >> 5;
        for (int d = dgrp; d < 512; d += 16)
            __stcs(&out[O_ZQST + (size_t)n * C_DIM * T_DIM + (size_t)d * T_DIM + t0 + lane],
                   s[lane * SG_STRIDE + d]);
    }

    red[tid] = cacc;
    __syncthreads();
    for (int sft = 256; sft > 0; sft >>= 1) {
        if (tid < sft) red[tid] += red[tid + sft];
        __syncthreads();
    }
    float cblock = red[0];
    __syncthreads();
    red[tid] = sacc;
    __syncthreads();
    for (int sft = 256; sft > 0; sft >>= 1) {
        if (tid < sft) red[tid] += red[tid + sft];
        __syncthreads();
    }
    if (tid == 0) {
        int bid = blockIdx.y * gridDim.x + blockIdx.x;
        g_cpart[bid] = cblock;
        g_spart[bid] = red[0];
    }
}

__global__ void loss_kernel(float* __restrict__ out) {
    __shared__ double rc[256], rs[256];
    int tid = threadIdx.x;
    double c = 0.0, s = 0.0;
    for (int i = tid; i < NUM_GATHER_BLOCKS; i += 256) {
        c += (double)g_cpart[i];
        s += (double)g_spart[i];
    }
    rc[tid] = c; rs[tid] = s;
    __syncthreads();
    for (int sft = 128; sft > 0; sft >>= 1) {
        if (tid < sft) { rc[tid] += rc[tid + sft]; rs[tid] += rs[tid + sft]; }
        __syncthreads();
    }
    if (tid == 0) {
        double MD = (double)M_ROWS * (double)D_DIM;
        out[O_COMMIT] = (float)(2.0 * rc[0] / MD);
        out[O_SOM]    = (float)(rs[0] / (MD * 5.0));
    }
}

// ---------------------------------------------------------------------------
extern "C" void kernel_launch(void* const* d_in, const int* in_sizes, int n_in,
                              void* d_out, int out_size) {
    const float* x = (const float*)d_in[0];
    const float* E = (const float*)d_in[1];
    float* out = (float*)d_out;

    static int init = 0;
    if (!init) {
        cudaFuncSetAttribute(mma_dist_kernel,
                             cudaFuncAttributeMaxDynamicSharedMemorySize, DYN_SMEM);
        cudaFuncSetAttribute(gather_kernel,
                             cudaFuncAttributeMaxDynamicSharedMemorySize, GATHER_SMEM);
        init = 1;
    }

    dim3 gz(T_DIM / 32, C_DIM / 64, N_B);
    prep_z_kernel<<<gz, 256>>>(x);
    esq_kernel<<<K_CODES, 128>>>(E);
    zsq_combine_kernel<<<M_ROWS / 256, 256>>>();
    dim3 gd(K_CODES / BN, M_ROWS / BM);
    mma_dist_kernel<<<gd, 128, DYN_SMEM>>>(out);
    fixup_kernel<<<M_ROWS / 8, 256>>>(E, out);
    dim3 g(T_DIM / 32, N_B);
    gather_kernel<<<g, 512, GATHER_SMEM>>>(E, out);
    loss_kernel<<<1, 256>>>(out);
}